// round 10
// baseline (speedup 1.0000x reference)
#include <cuda_runtime.h>
#include <cuda_bf16.h>
#include <cuda_fp16.h>
#include <math.h>
#include <stdint.h>

#define F 256
#define NW 512           // fused B width: [W_self | W]
#define N_MAX 50048
#define E_MAX 800256

// -------- device scratch (zero-initialized at module load; every launch
// restores the zero invariant for g_cnt/g_outd/g_sstate) --------
__device__ float g_sin[N_MAX];               // in_deg^-1/2
__device__ float g_outr[N_MAX];              // out_deg^-1/2
__device__ int   g_cnt[N_MAX];
__device__ int   g_outd[N_MAX];
__device__ int   g_fill[N_MAX];
__device__ int   g_roff[N_MAX + 1];
__device__ int   g_esrc[E_MAX];
__device__ float g_esc[E_MAX];
__device__ int   g_sstate[64];               // lookback scan state

__device__ __half g_featH[(size_t)N_MAX * F];       // fp16 hi
__device__ __half g_featL[(size_t)N_MAX * F];       // fp16 residual
__device__ __half g_wb[F * NW];                     // [k][n512] = [W_self | W]
__device__ __half g_h0[(size_t)N_MAX * F];          // feature@W_self (fp16)
__device__ __half g_h1[(size_t)N_MAX * F];          // feature@W      (fp16)

// -------- helpers --------
__device__ __forceinline__ uint32_t sptr(const void* p) {
    return (uint32_t)__cvta_generic_to_shared(p);
}
__device__ __forceinline__ void ldsm4(unsigned r[4], uint32_t a) {
    asm volatile("ldmatrix.sync.aligned.m8n8.x4.shared.b16 {%0,%1,%2,%3}, [%4];\n"
        : "=r"(r[0]), "=r"(r[1]), "=r"(r[2]), "=r"(r[3]) : "r"(a));
}
__device__ __forceinline__ void ldsm4t(unsigned r[4], uint32_t a) {
    asm volatile("ldmatrix.sync.aligned.m8n8.x4.trans.shared.b16 {%0,%1,%2,%3}, [%4];\n"
        : "=r"(r[0]), "=r"(r[1]), "=r"(r[2]), "=r"(r[3]) : "r"(a));
}
__device__ __forceinline__ void mma_f16(float* d, const unsigned a[4],
                                        unsigned b0, unsigned b1) {
    asm volatile(
        "mma.sync.aligned.m16n8k16.row.col.f32.f16.f16.f32 "
        "{%0,%1,%2,%3}, {%4,%5,%6,%7}, {%8,%9}, {%0,%1,%2,%3};\n"
        : "+f"(d[0]), "+f"(d[1]), "+f"(d[2]), "+f"(d[3])
        : "r"(a[0]), "r"(a[1]), "r"(a[2]), "r"(a[3]), "r"(b0), "r"(b1));
}
__device__ __forceinline__ void cp16(uint32_t dst, const void* src) {
    asm volatile("cp.async.cg.shared.global [%0], [%1], 16;\n" :: "r"(dst), "l"(src));
}
__device__ __forceinline__ void cp16z(uint32_t dst, const void* src, int sz) {
    asm volatile("cp.async.cg.shared.global [%0], [%1], 16, %2;\n"
                 :: "r"(dst), "l"(src), "r"(sz));
}
__device__ __forceinline__ void cp_commit() {
    asm volatile("cp.async.commit_group;\n" ::: "memory");
}
__device__ __forceinline__ void cp_wait1() {
    asm volatile("cp.async.wait_group 1;\n" ::: "memory");
}
__device__ __forceinline__ void cp_wait0() {
    asm volatile("cp.async.wait_group 0;\n" ::: "memory");
}

// ---------------- fused: hist | convert feature | convert W ----------------
__global__ void phaseA_kernel(const int* __restrict__ src,
                              const int* __restrict__ dst,
                              const float* __restrict__ feat,
                              const float* __restrict__ Ws,
                              const float* __restrict__ Wn,
                              int e, int q, int HB, int CB) {
    int b = blockIdx.x, t = threadIdx.x;
    if (b < HB) {
        int i = b * 256 + t;
        if (i < e) {
            atomicAdd(&g_cnt[dst[i]], 1);
            atomicAdd(&g_outd[src[i]], 1);
        }
    } else if (b < HB + CB) {
        int i = (b - HB) * 256 + t;
        if (i < q) {
            float4 v = ((const float4*)feat)[i];
            __half h0 = __float2half_rn(v.x), h1 = __float2half_rn(v.y);
            __half h2 = __float2half_rn(v.z), h3 = __float2half_rn(v.w);
            __half l0 = __float2half_rn(v.x - __half2float(h0));
            __half l1 = __float2half_rn(v.y - __half2float(h1));
            __half l2 = __float2half_rn(v.z - __half2float(h2));
            __half l3 = __float2half_rn(v.w - __half2float(h3));
            __half2 H0 = __halves2half2(h0, h1), H1 = __halves2half2(h2, h3);
            __half2 L0 = __halves2half2(l0, l1), L1 = __halves2half2(l2, l3);
            ((uint2*)g_featH)[i] = make_uint2(*(unsigned*)&H0, *(unsigned*)&H1);
            ((uint2*)g_featL)[i] = make_uint2(*(unsigned*)&L0, *(unsigned*)&L1);
        }
    } else {
        int i = (b - HB - CB) * 256 + t;
        if (i < F * F) {
            int k = i >> 8, nn = i & 255;
            g_wb[k * NW + nn]       = __float2half_rn(Ws[i]);
            g_wb[k * NW + 256 + nn] = __float2half_rn(Wn[i]);
        }
    }
}

// ---------------- single-pass scan (decoupled lookback, <=64 blocks) -------
// Also restores g_cnt/g_outd to zero for the next graph replay.
__global__ void __launch_bounds__(1024)
scan_fused_kernel(int n) {
    __shared__ int sh[1024];
    __shared__ int s_pre;
    int b = blockIdx.x, t = threadIdx.x;
    int i = b * 1024 + t;
    int cnt = (i < n) ? g_cnt[i] : 0;
    int outd = (i < n) ? g_outd[i] : 0;
    sh[t] = cnt; __syncthreads();
    #pragma unroll
    for (int off = 1; off < 1024; off <<= 1) {
        int x = sh[t];
        if (t >= off) x += sh[t - off];
        __syncthreads();
        sh[t] = x;
        __syncthreads();
    }
    int incl = sh[t];
    int total = sh[1023];

    if (t == 0) {
        volatile int* st = g_sstate;
        if (b == 0) {
            st[0] = (total << 2) | 2;
            s_pre = 0;
        } else {
            st[b] = (total << 2) | 1;          // publish aggregate
            int pre = 0;
            int j = b - 1;
            while (j >= 0) {
                int v = st[j];
                int f = v & 3;
                if (f == 2) { pre += (v >> 2); break; }
                if (f == 1) { pre += (v >> 2); --j; }
            }
            st[b] = ((total + pre) << 2) | 2;  // upgrade to inclusive
            s_pre = pre;
        }
    }
    __syncthreads();
    int incl_g = incl + s_pre;
    if (i < n) {
        g_roff[i + 1] = incl_g;
        g_fill[i] = incl_g - cnt;
        g_outr[i] = rsqrtf(fmaxf((float)outd, 1.0f));
        g_sin[i]  = rsqrtf(fmaxf((float)cnt, 1.0f));
        g_cnt[i]  = 0;                         // restore zero invariant
        g_outd[i] = 0;
        if (i == 0) g_roff[0] = 0;
    }
}

// ---------------- fused GEMM + fill (block-split, 2:1 interleave) ----------
// Every third block (b%3==2, while fill blocks remain) handles 1024 edges of
// the CSR scatter; the rest are 128x128 GEMM tiles. Fill's L2-bound work
// rides in the GEMM's memory slack within each wave.
#define A_STRIDE 40
#define B_STRIDE 136
#define ST_ELEMS 14592           // 2*128*40 + 32*136
#define AH_OFF(s) ((s) * ST_ELEMS)
#define AL_OFF(s) ((s) * ST_ELEMS + 5120)
#define BH_OFF(s) ((s) * ST_ELEMS + 10240)
#define NSTAGE 3
#define SMEM_DYN (NSTAGE * ST_ELEMS * 2)

__device__ __forceinline__ void load_stage(uint32_t sb, int stage, int it,
                                           int mBase, int nBase, int n, int tid,
                                           bool needL) {
    int k0 = it * 32;
    #pragma unroll
    for (int u = 0; u < 2; ++u) {
        int idx = u * 256 + tid;
        int row = idx >> 2, un = idx & 3;
        int gr = mBase + row;
        int grc = min(gr, n - 1);
        size_t go = (size_t)grc * F + k0 + un * 8;
        int sz = (gr < n) ? 16 : 0;
        uint32_t doff = (uint32_t)(row * A_STRIDE + un * 8) * 2;
        cp16z(sb + (uint32_t)AH_OFF(stage) * 2 + doff, g_featH + go, sz);
        if (needL)
            cp16z(sb + (uint32_t)AL_OFF(stage) * 2 + doff, g_featL + go, sz);
    }
    #pragma unroll
    for (int u = 0; u < 2; ++u) {
        int idx = u * 256 + tid;
        int row = idx >> 4, un = idx & 15;
        size_t go = (size_t)(k0 + row) * NW + nBase + un * 8;
        uint32_t doff = (uint32_t)(row * B_STRIDE + un * 8) * 2;
        cp16(sb + (uint32_t)BH_OFF(stage) * 2 + doff, g_wb + go);
    }
}

__global__ void __launch_bounds__(256, 2)
gemmfill_kernel(const int* __restrict__ src,
                const int* __restrict__ dst,
                const float* __restrict__ e_w,
                float* __restrict__ out_tail,
                int n, int e, int FB) {
    int b = blockIdx.x, tid = threadIdx.x;

    // ----- fill path -----
    bool is_fill = ((b % 3) == 2) && ((b / 3) < FB);
    if (is_fill) {
        int fidx = b / 3;
        if (fidx == 0 && tid < 64) g_sstate[tid] = 0;   // restore for next replay
        int basei = fidx * 1024 + tid;
        #pragma unroll
        for (int u = 0; u < 4; ++u) {
            int i = basei + u * 256;
            if (i < e) {
                float w = e_w[i];
                int s = src[i];
                int p = atomicAdd(&g_fill[dst[i]], 1);
                g_esrc[p] = s;
                g_esc[p] = w * g_outr[s];
                out_tail[i] = w;           // e_w passthrough output
            }
        }
        return;
    }
    int fills_before = min((b + 1) / 3, FB);
    int t = b - fills_before;              // gemm tile index

    extern __shared__ __align__(128) char smraw[];
    __half* base = (__half*)smraw;
    uint32_t sb = sptr(smraw);

    int wid = tid >> 5, lane = tid & 31;
    int wm = wid & 3, wn = wid >> 2;
    int mBase = (t >> 2) * 128;
    int tn = t & 3;
    int nBase = tn * 128;
    const bool needL = (tn < 2);           // 2-term split only for the h_s half

    float acc[2][8][4];
    #pragma unroll
    for (int i = 0; i < 2; ++i)
        #pragma unroll
        for (int j = 0; j < 8; ++j)
            #pragma unroll
            for (int q = 0; q < 4; ++q) acc[i][j][q] = 0.f;

    load_stage(sb, 0, 0, mBase, nBase, n, tid, needL); cp_commit();
    load_stage(sb, 1, 1, mBase, nBase, n, tid, needL); cp_commit();

    #pragma unroll 1
    for (int it = 0; it < 8; ++it) {
        if (it < 7) cp_wait1(); else cp_wait0();
        __syncthreads();
        int st = it % NSTAGE;
        #pragma unroll
        for (int kt = 0; kt < 2; ++kt) {
            int ks = kt * 16;
            unsigned aH[2][4], aL[2][4];
            #pragma unroll
            for (int mt = 0; mt < 2; ++mt) {
                int r = wm * 32 + mt * 16 + (lane & 15);
                int c = ks + (lane >> 4) * 8;
                ldsm4(aH[mt], sptr(base + AH_OFF(st) + r * A_STRIDE + c));
                if (needL)
                    ldsm4(aL[mt], sptr(base + AL_OFF(st) + r * A_STRIDE + c));
            }
            #pragma unroll
            for (int nc = 0; nc < 4; ++nc) {
                int rB = ks + (lane & 15);
                int cB = wn * 64 + nc * 16 + (lane >> 4) * 8;
                unsigned bH[4];
                ldsm4t(bH, sptr(base + BH_OFF(st) + rB * B_STRIDE + cB));
                #pragma unroll
                for (int mt = 0; mt < 2; ++mt) {
                    mma_f16(acc[mt][nc * 2],     aH[mt], bH[0], bH[1]);
                    mma_f16(acc[mt][nc * 2 + 1], aH[mt], bH[2], bH[3]);
                    if (needL) {
                        mma_f16(acc[mt][nc * 2],     aL[mt], bH[0], bH[1]);
                        mma_f16(acc[mt][nc * 2 + 1], aL[mt], bH[2], bH[3]);
                    }
                }
            }
        }
        if (it + 2 < 8) {
            load_stage(sb, (it + 2) % NSTAGE, it + 2, mBase, nBase, n, tid, needL);
            cp_commit();
        }
    }

    // epilogue: fp16 to g_h0 (tn<2) or g_h1 (tn>=2)
    __half* dstp = (tn < 2) ? g_h0 : g_h1;
    #pragma unroll
    for (int mt = 0; mt < 2; ++mt) {
        int r0 = mBase + wm * 32 + mt * 16 + (lane >> 2);
        int r1 = r0 + 8;
        #pragma unroll
        for (int nt = 0; nt < 8; ++nt) {
            int cl = wn * 64 + nt * 8 + (lane & 3) * 2;
            int c = (tn & 1) * 128 + cl;
            float* d = acc[mt][nt];
            if (r0 < n) {
                __half2 v = __floats2half2_rn(d[0], d[1]);
                *(unsigned*)(dstp + (size_t)r0 * F + c) = *(unsigned*)&v;
            }
            if (r1 < n) {
                __half2 v = __floats2half2_rn(d[2], d[3]);
                *(unsigned*)(dstp + (size_t)r1 * F + c) = *(unsigned*)&v;
            }
        }
    }
}

// ---------------- final: out = h0 + si*(S . h1) + si*b (write-only out) ----
__global__ void __launch_bounds__(512)
final_kernel(const float* __restrict__ bias, float* __restrict__ out, int n) {
    int row  = blockIdx.x * 16 + (threadIdx.x >> 5);
    int lane = threadIdx.x & 31;
    if (row >= n) return;
    int beg = g_roff[row], end = g_roff[row + 1];
    float a[8];
    #pragma unroll
    for (int j = 0; j < 8; ++j) a[j] = 0.f;
    for (int base = beg; base < end; base += 32) {
        int m = min(32, end - base);
        int sE = 0; float cE = 0.f;
        if (lane < m) { sE = g_esrc[base + lane]; cE = g_esc[base + lane]; }
        #pragma unroll 4
        for (int j = 0; j < m; ++j) {
            int   ss = __shfl_sync(0xffffffffu, sE, j);
            float sc = __shfl_sync(0xffffffffu, cE, j);
            uint4 d = *(const uint4*)(g_h1 + (size_t)ss * F + lane * 8);
            float2 f0 = __half22float2(*(__half2*)&d.x);
            float2 f1 = __half22float2(*(__half2*)&d.y);
            float2 f2 = __half22float2(*(__half2*)&d.z);
            float2 f3 = __half22float2(*(__half2*)&d.w);
            a[0] += f0.x * sc; a[1] += f0.y * sc;
            a[2] += f1.x * sc; a[3] += f1.y * sc;
            a[4] += f2.x * sc; a[5] += f2.y * sc;
            a[6] += f3.x * sc; a[7] += f3.y * sc;
        }
    }
    float si = g_sin[row];
    uint4 h = *(const uint4*)(g_h0 + (size_t)row * F + lane * 8);
    float2 s0 = __half22float2(*(__half2*)&h.x);
    float2 s1 = __half22float2(*(__half2*)&h.y);
    float2 s2 = __half22float2(*(__half2*)&h.z);
    float2 s3 = __half22float2(*(__half2*)&h.w);
    float4 b0 = *(const float4*)(bias + lane * 8);
    float4 b1 = *(const float4*)(bias + lane * 8 + 4);
    float4 o0, o1;
    o0.x = s0.x + si * (a[0] + b0.x); o0.y = s0.y + si * (a[1] + b0.y);
    o0.z = s1.x + si * (a[2] + b0.z); o0.w = s1.y + si * (a[3] + b0.w);
    o1.x = s2.x + si * (a[4] + b1.x); o1.y = s2.y + si * (a[5] + b1.y);
    o1.z = s3.x + si * (a[6] + b1.z); o1.w = s3.y + si * (a[7] + b1.w);
    float* op = out + (size_t)row * F + lane * 8;
    *(float4*)(op)     = o0;
    *(float4*)(op + 4) = o1;
}

// ---------------- launch ----------------
extern "C" void kernel_launch(void* const* d_in, const int* in_sizes, int n_in,
                              void* d_out, int out_size) {
    const float* feature = (const float*)d_in[0];
    const float* e_w     = (const float*)d_in[1];
    const float* W_self  = (const float*)d_in[4];
    const float* W       = (const float*)d_in[5];
    const float* b       = (const float*)d_in[6];
    const int*   src     = (const int*)d_in[7];
    const int*   dst     = (const int*)d_in[8];
    float*       out     = (float*)d_out;

    int n = in_sizes[0] / F;
    int e = in_sizes[1];
    int q = n * (F / 4);

    static bool init = false;
    if (!init) {
        cudaFuncSetAttribute(gemmfill_kernel,
                             cudaFuncAttributeMaxDynamicSharedMemorySize, SMEM_DYN);
        init = true;
    }

    // K1: fused hist | convert feature | convert W
    int HB = (e + 255) / 256;
    int CB = (q + 255) / 256;
    int WB = (F * F + 255) / 256;
    phaseA_kernel<<<HB + CB + WB, 256>>>(src, dst, feature, W_self, W,
                                         e, q, HB, CB);

    // K2: single-pass scan (+ restores count buffers to zero)
    int NB = (n + 1023) / 1024;     // <= 64
    scan_fused_kernel<<<NB, 1024>>>(n);

    // K3: fused GEMM + CSR fill (interleaved block split)
    int NT = ((n + 127) / 128) * 4;
    int FB = (e + 1023) / 1024;
    gemmfill_kernel<<<NT + FB, 256, SMEM_DYN>>>(src, dst, e_w,
                                                out + (size_t)n * F,
                                                n, e, FB);

    // K4: final gather + epilogue
    final_kernel<<<(n + 15) / 16, 512>>>(b, out, n);
}

// round 11
// speedup vs baseline: 1.0863x; 1.0863x over previous
#include <cuda_runtime.h>
#include <cuda_bf16.h>
#include <cuda_fp16.h>
#include <math.h>
#include <stdint.h>

#define F 256
#define NW 512           // fused B width: [W_self | W]
#define N_MAX 50048
#define E_MAX 800256

// -------- device scratch (zero-initialized at module load; every launch
// restores the zero invariant for g_cnt/g_outd/g_sstate) --------
__device__ float g_sin[N_MAX];               // in_deg^-1/2
__device__ float g_outr[N_MAX];              // out_deg^-1/2
__device__ int   g_cnt[N_MAX];
__device__ int   g_outd[N_MAX];
__device__ int   g_fill[N_MAX];
__device__ int   g_roff[N_MAX + 1];
__device__ int   g_esrc[E_MAX];
__device__ float g_esc[E_MAX];
__device__ int   g_sstate[64];               // lookback scan state

__device__ __half g_featH[(size_t)N_MAX * F];       // fp16 hi
__device__ __half g_featL[(size_t)N_MAX * F];       // fp16 residual
__device__ __half g_wb[F * NW];                     // [k][n512] = [W_self | W]
__device__ __half g_h0[(size_t)N_MAX * F];          // feature@W_self (fp16)
__device__ __half g_h1[(size_t)N_MAX * F];          // feature@W      (fp16)

// -------- helpers --------
__device__ __forceinline__ uint32_t sptr(const void* p) {
    return (uint32_t)__cvta_generic_to_shared(p);
}
__device__ __forceinline__ void ldsm4(unsigned r[4], uint32_t a) {
    asm volatile("ldmatrix.sync.aligned.m8n8.x4.shared.b16 {%0,%1,%2,%3}, [%4];\n"
        : "=r"(r[0]), "=r"(r[1]), "=r"(r[2]), "=r"(r[3]) : "r"(a));
}
__device__ __forceinline__ void ldsm4t(unsigned r[4], uint32_t a) {
    asm volatile("ldmatrix.sync.aligned.m8n8.x4.trans.shared.b16 {%0,%1,%2,%3}, [%4];\n"
        : "=r"(r[0]), "=r"(r[1]), "=r"(r[2]), "=r"(r[3]) : "r"(a));
}
__device__ __forceinline__ void mma_f16(float* d, const unsigned a[4],
                                        unsigned b0, unsigned b1) {
    asm volatile(
        "mma.sync.aligned.m16n8k16.row.col.f32.f16.f16.f32 "
        "{%0,%1,%2,%3}, {%4,%5,%6,%7}, {%8,%9}, {%0,%1,%2,%3};\n"
        : "+f"(d[0]), "+f"(d[1]), "+f"(d[2]), "+f"(d[3])
        : "r"(a[0]), "r"(a[1]), "r"(a[2]), "r"(a[3]), "r"(b0), "r"(b1));
}
__device__ __forceinline__ void cp16(uint32_t dst, const void* src) {
    asm volatile("cp.async.cg.shared.global [%0], [%1], 16;\n" :: "r"(dst), "l"(src));
}
__device__ __forceinline__ void cp16z(uint32_t dst, const void* src, int sz) {
    asm volatile("cp.async.cg.shared.global [%0], [%1], 16, %2;\n"
                 :: "r"(dst), "l"(src), "r"(sz));
}
__device__ __forceinline__ void cp_commit() {
    asm volatile("cp.async.commit_group;\n" ::: "memory");
}
__device__ __forceinline__ void cp_wait1() {
    asm volatile("cp.async.wait_group 1;\n" ::: "memory");
}
__device__ __forceinline__ void cp_wait0() {
    asm volatile("cp.async.wait_group 0;\n" ::: "memory");
}

// ---------------- fused: hist | convert feature | convert W ----------------
__global__ void phaseA_kernel(const int* __restrict__ src,
                              const int* __restrict__ dst,
                              const float* __restrict__ feat,
                              const float* __restrict__ Ws,
                              const float* __restrict__ Wn,
                              int e, int q, int HB, int CB) {
    int b = blockIdx.x, t = threadIdx.x;
    if (b < HB) {
        int i = b * 256 + t;
        if (i < e) {
            atomicAdd(&g_cnt[dst[i]], 1);
            atomicAdd(&g_outd[src[i]], 1);
        }
    } else if (b < HB + CB) {
        int i = (b - HB) * 256 + t;
        if (i < q) {
            float4 v = ((const float4*)feat)[i];
            __half h0 = __float2half_rn(v.x), h1 = __float2half_rn(v.y);
            __half h2 = __float2half_rn(v.z), h3 = __float2half_rn(v.w);
            __half l0 = __float2half_rn(v.x - __half2float(h0));
            __half l1 = __float2half_rn(v.y - __half2float(h1));
            __half l2 = __float2half_rn(v.z - __half2float(h2));
            __half l3 = __float2half_rn(v.w - __half2float(h3));
            __half2 H0 = __halves2half2(h0, h1), H1 = __halves2half2(h2, h3);
            __half2 L0 = __halves2half2(l0, l1), L1 = __halves2half2(l2, l3);
            ((uint2*)g_featH)[i] = make_uint2(*(unsigned*)&H0, *(unsigned*)&H1);
            ((uint2*)g_featL)[i] = make_uint2(*(unsigned*)&L0, *(unsigned*)&L1);
        }
    } else {
        int i = (b - HB - CB) * 256 + t;
        if (i < F * F) {
            int k = i >> 8, nn = i & 255;
            g_wb[k * NW + nn]       = __float2half_rn(Ws[i]);
            g_wb[k * NW + 256 + nn] = __float2half_rn(Wn[i]);
        }
    }
}

// ---------------- single-pass scan (warp-shuffle + decoupled lookback) -----
// Also restores g_cnt/g_outd to zero for the next graph replay.
__global__ void __launch_bounds__(1024)
scan_fused_kernel(int n) {
    __shared__ int warpsum[32];
    __shared__ int s_pre;
    int b = blockIdx.x, t = threadIdx.x;
    int lane = t & 31, w = t >> 5;
    int i = b * 1024 + t;
    int cnt  = (i < n) ? g_cnt[i] : 0;
    int outd = (i < n) ? g_outd[i] : 0;

    int x = cnt;
    #pragma unroll
    for (int off = 1; off < 32; off <<= 1) {
        int y = __shfl_up_sync(0xffffffffu, x, off);
        if (lane >= off) x += y;
    }
    if (lane == 31) warpsum[w] = x;
    __syncthreads();
    if (w == 0) {
        int v = warpsum[lane];
        #pragma unroll
        for (int off = 1; off < 32; off <<= 1) {
            int y = __shfl_up_sync(0xffffffffu, v, off);
            if (lane >= off) v += y;
        }
        warpsum[lane] = v;
    }
    __syncthreads();
    int incl = x + (w ? warpsum[w - 1] : 0);
    int total = warpsum[31];

    if (t == 0) {
        volatile int* st = g_sstate;
        if (b == 0) {
            st[0] = (total << 2) | 2;
            s_pre = 0;
        } else {
            st[b] = (total << 2) | 1;          // publish aggregate
            int pre = 0;
            int j = b - 1;
            while (j >= 0) {
                int v = st[j];
                int f = v & 3;
                if (f == 2) { pre += (v >> 2); break; }
                if (f == 1) { pre += (v >> 2); --j; }
            }
            st[b] = ((total + pre) << 2) | 2;  // upgrade to inclusive
            s_pre = pre;
        }
    }
    __syncthreads();
    int incl_g = incl + s_pre;
    if (i < n) {
        g_roff[i + 1] = incl_g;
        g_fill[i] = incl_g - cnt;
        g_outr[i] = rsqrtf(fmaxf((float)outd, 1.0f));
        g_sin[i]  = rsqrtf(fmaxf((float)cnt, 1.0f));
        g_cnt[i]  = 0;                         // restore zero invariant
        g_outd[i] = 0;
        if (i == 0) g_roff[0] = 0;
    }
}

// ---------------- GEMM; each CTA also fills its edge slice after epilogue --
#define A_STRIDE 40
#define B_STRIDE 136
#define ST_ELEMS 14592           // 2*128*40 + 32*136
#define AH_OFF(s) ((s) * ST_ELEMS)
#define AL_OFF(s) ((s) * ST_ELEMS + 5120)
#define BH_OFF(s) ((s) * ST_ELEMS + 10240)
#define NSTAGE 3
#define SMEM_DYN (NSTAGE * ST_ELEMS * 2)

__device__ __forceinline__ void load_stage(uint32_t sb, int stage, int it,
                                           int mBase, int nBase, int n, int tid,
                                           bool needL) {
    int k0 = it * 32;
    #pragma unroll
    for (int u = 0; u < 2; ++u) {
        int idx = u * 256 + tid;
        int row = idx >> 2, un = idx & 3;
        int gr = mBase + row;
        int grc = min(gr, n - 1);
        size_t go = (size_t)grc * F + k0 + un * 8;
        int sz = (gr < n) ? 16 : 0;
        uint32_t doff = (uint32_t)(row * A_STRIDE + un * 8) * 2;
        cp16z(sb + (uint32_t)AH_OFF(stage) * 2 + doff, g_featH + go, sz);
        if (needL)
            cp16z(sb + (uint32_t)AL_OFF(stage) * 2 + doff, g_featL + go, sz);
    }
    #pragma unroll
    for (int u = 0; u < 2; ++u) {
        int idx = u * 256 + tid;
        int row = idx >> 4, un = idx & 15;
        size_t go = (size_t)(k0 + row) * NW + nBase + un * 8;
        uint32_t doff = (uint32_t)(row * B_STRIDE + un * 8) * 2;
        cp16(sb + (uint32_t)BH_OFF(stage) * 2 + doff, g_wb + go);
    }
}

__global__ void __launch_bounds__(256, 2)
gemmfill_kernel(const int* __restrict__ src,
                const int* __restrict__ dst,
                const float* __restrict__ e_w,
                float* __restrict__ out_tail,
                int n, int e, int EPB) {
    extern __shared__ __align__(128) char smraw[];
    __half* base = (__half*)smraw;
    uint32_t sb = sptr(smraw);

    int b = blockIdx.x, tid = threadIdx.x;
    int wid = tid >> 5, lane = tid & 31;
    int wm = wid & 3, wn = wid >> 2;
    int t = b;
    int mBase = (t >> 2) * 128;
    int tn = t & 3;
    int nBase = tn * 128;
    const bool needL = (tn < 2);           // 2-term split only for the h_s half

    float acc[2][8][4];
    #pragma unroll
    for (int i = 0; i < 2; ++i)
        #pragma unroll
        for (int j = 0; j < 8; ++j)
            #pragma unroll
            for (int q = 0; q < 4; ++q) acc[i][j][q] = 0.f;

    load_stage(sb, 0, 0, mBase, nBase, n, tid, needL); cp_commit();
    load_stage(sb, 1, 1, mBase, nBase, n, tid, needL); cp_commit();

    #pragma unroll 1
    for (int it = 0; it < 8; ++it) {
        if (it < 7) cp_wait1(); else cp_wait0();
        __syncthreads();
        int st = it % NSTAGE;
        #pragma unroll
        for (int kt = 0; kt < 2; ++kt) {
            int ks = kt * 16;
            unsigned aH[2][4], aL[2][4];
            #pragma unroll
            for (int mt = 0; mt < 2; ++mt) {
                int r = wm * 32 + mt * 16 + (lane & 15);
                int c = ks + (lane >> 4) * 8;
                ldsm4(aH[mt], sptr(base + AH_OFF(st) + r * A_STRIDE + c));
                if (needL)
                    ldsm4(aL[mt], sptr(base + AL_OFF(st) + r * A_STRIDE + c));
            }
            #pragma unroll
            for (int nc = 0; nc < 4; ++nc) {
                int rB = ks + (lane & 15);
                int cB = wn * 64 + nc * 16 + (lane >> 4) * 8;
                unsigned bH[4];
                ldsm4t(bH, sptr(base + BH_OFF(st) + rB * B_STRIDE + cB));
                #pragma unroll
                for (int mt = 0; mt < 2; ++mt) {
                    mma_f16(acc[mt][nc * 2],     aH[mt], bH[0], bH[1]);
                    mma_f16(acc[mt][nc * 2 + 1], aH[mt], bH[2], bH[3]);
                    if (needL) {
                        mma_f16(acc[mt][nc * 2],     aL[mt], bH[0], bH[1]);
                        mma_f16(acc[mt][nc * 2 + 1], aL[mt], bH[2], bH[3]);
                    }
                }
            }
        }
        if (it + 2 < 8) {
            load_stage(sb, (it + 2) % NSTAGE, it + 2, mBase, nBase, n, tid, needL);
            cp_commit();
        }
    }

    // epilogue: fp16 to g_h0 (tn<2) or g_h1 (tn>=2)
    __half* dstp = (tn < 2) ? g_h0 : g_h1;
    #pragma unroll
    for (int mt = 0; mt < 2; ++mt) {
        int r0 = mBase + wm * 32 + mt * 16 + (lane >> 2);
        int r1 = r0 + 8;
        #pragma unroll
        for (int nt = 0; nt < 8; ++nt) {
            int cl = wn * 64 + nt * 8 + (lane & 3) * 2;
            int c = (tn & 1) * 128 + cl;
            float* d = acc[mt][nt];
            if (r0 < n) {
                __half2 v = __floats2half2_rn(d[0], d[1]);
                *(unsigned*)(dstp + (size_t)r0 * F + c) = *(unsigned*)&v;
            }
            if (r1 < n) {
                __half2 v = __floats2half2_rn(d[2], d[3]);
                *(unsigned*)(dstp + (size_t)r1 * F + c) = *(unsigned*)&v;
            }
        }
    }

    // ----- CSR fill: this CTA's edge slice (no extra residency cost) -----
    if (b == 0 && tid < 64) g_sstate[tid] = 0;   // restore for next replay
    int e0 = b * EPB;
    #pragma unroll 2
    for (int i = e0 + tid; i < min(e0 + EPB, e); i += 256) {
        float w = e_w[i];
        int s = src[i];
        int p = atomicAdd(&g_fill[dst[i]], 1);
        g_esrc[p] = s;
        g_esc[p] = w * g_outr[s];
        out_tail[i] = w;                 // e_w passthrough output
    }
}

// ---------------- final: out = h0 + si*(S . h1) + si*b (MLP=8 gather) ------
__global__ void __launch_bounds__(256)
final_kernel(const float* __restrict__ bias, float* __restrict__ out, int n) {
    int row  = blockIdx.x * 8 + (threadIdx.x >> 5);
    int lane = threadIdx.x & 31;
    if (row >= n) return;
    int beg = g_roff[row], end = g_roff[row + 1];
    float a[8];
    #pragma unroll
    for (int j = 0; j < 8; ++j) a[j] = 0.f;

    for (int base = beg; base < end; base += 32) {
        int m = min(32, end - base);
        int sE = 0; float cE = 0.f;
        if (lane < m) { sE = g_esrc[base + lane]; cE = g_esc[base + lane]; }
        int j = 0;
        for (; j + 8 <= m; j += 8) {
            uint4 d[8];
            #pragma unroll
            for (int u = 0; u < 8; ++u) {
                int ss = __shfl_sync(0xffffffffu, sE, j + u);
                d[u] = *(const uint4*)(g_h1 + (size_t)ss * F + lane * 8);
            }
            #pragma unroll
            for (int u = 0; u < 8; ++u) {
                float sc = __shfl_sync(0xffffffffu, cE, j + u);
                float2 f0 = __half22float2(*(__half2*)&d[u].x);
                float2 f1 = __half22float2(*(__half2*)&d[u].y);
                float2 f2 = __half22float2(*(__half2*)&d[u].z);
                float2 f3 = __half22float2(*(__half2*)&d[u].w);
                a[0] += f0.x * sc; a[1] += f0.y * sc;
                a[2] += f1.x * sc; a[3] += f1.y * sc;
                a[4] += f2.x * sc; a[5] += f2.y * sc;
                a[6] += f3.x * sc; a[7] += f3.y * sc;
            }
        }
        for (; j < m; ++j) {
            int   ss = __shfl_sync(0xffffffffu, sE, j);
            float sc = __shfl_sync(0xffffffffu, cE, j);
            uint4 d = *(const uint4*)(g_h1 + (size_t)ss * F + lane * 8);
            float2 f0 = __half22float2(*(__half2*)&d.x);
            float2 f1 = __half22float2(*(__half2*)&d.y);
            float2 f2 = __half22float2(*(__half2*)&d.z);
            float2 f3 = __half22float2(*(__half2*)&d.w);
            a[0] += f0.x * sc; a[1] += f0.y * sc;
            a[2] += f1.x * sc; a[3] += f1.y * sc;
            a[4] += f2.x * sc; a[5] += f2.y * sc;
            a[6] += f3.x * sc; a[7] += f3.y * sc;
        }
    }

    float si = g_sin[row];
    uint4 h = *(const uint4*)(g_h0 + (size_t)row * F + lane * 8);
    float2 s0 = __half22float2(*(__half2*)&h.x);
    float2 s1 = __half22float2(*(__half2*)&h.y);
    float2 s2 = __half22float2(*(__half2*)&h.z);
    float2 s3 = __half22float2(*(__half2*)&h.w);
    float4 b0 = *(const float4*)(bias + lane * 8);
    float4 b1 = *(const float4*)(bias + lane * 8 + 4);
    float4 o0, o1;
    o0.x = s0.x + si * (a[0] + b0.x); o0.y = s0.y + si * (a[1] + b0.y);
    o0.z = s1.x + si * (a[2] + b0.z); o0.w = s1.y + si * (a[3] + b0.w);
    o1.x = s2.x + si * (a[4] + b1.x); o1.y = s2.y + si * (a[5] + b1.y);
    o1.z = s3.x + si * (a[6] + b1.z); o1.w = s3.y + si * (a[7] + b1.w);
    float* op = out + (size_t)row * F + lane * 8;
    *(float4*)(op)     = o0;
    *(float4*)(op + 4) = o1;
}

// ---------------- launch ----------------
extern "C" void kernel_launch(void* const* d_in, const int* in_sizes, int n_in,
                              void* d_out, int out_size) {
    const float* feature = (const float*)d_in[0];
    const float* e_w     = (const float*)d_in[1];
    const float* W_self  = (const float*)d_in[4];
    const float* W       = (const float*)d_in[5];
    const float* b       = (const float*)d_in[6];
    const int*   src     = (const int*)d_in[7];
    const int*   dst     = (const int*)d_in[8];
    float*       out     = (float*)d_out;

    int n = in_sizes[0] / F;
    int e = in_sizes[1];
    int q = n * (F / 4);

    static bool init = false;
    if (!init) {
        cudaFuncSetAttribute(gemmfill_kernel,
                             cudaFuncAttributeMaxDynamicSharedMemorySize, SMEM_DYN);
        init = true;
    }

    // K1: fused hist | convert feature | convert W
    int HB = (e + 255) / 256;
    int CB = (q + 255) / 256;
    int WB = (F * F + 255) / 256;
    phaseA_kernel<<<HB + CB + WB, 256>>>(src, dst, feature, W_self, W,
                                         e, q, HB, CB);

    // K2: single-pass scan (+ restores count buffers to zero)
    int NB = (n + 1023) / 1024;     // <= 64
    scan_fused_kernel<<<NB, 1024>>>(n);

    // K3: GEMM; each CTA fills its edge slice after its epilogue
    int NT = ((n + 127) / 128) * 4;
    int EPB = (e + NT - 1) / NT;
    gemmfill_kernel<<<NT, 256, SMEM_DYN>>>(src, dst, e_w,
                                           out + (size_t)n * F, n, e, EPB);

    // K4: final gather + epilogue (MLP=8)
    final_kernel<<<(n + 7) / 8, 256>>>(b, out, n);
}

// round 12
// speedup vs baseline: 1.2215x; 1.1245x over previous
#include <cuda_runtime.h>
#include <cuda_bf16.h>
#include <cuda_fp16.h>
#include <math.h>
#include <stdint.h>

#define F 256
#define NW 512           // fused B width: [W_self | W]
#define N_MAX 50048
#define E_MAX 800256

// -------- device scratch (zero-initialized at module load; every launch
// restores the zero invariant for g_cnt/g_outd/g_sstate) --------
__device__ float g_sin[N_MAX];               // in_deg^-1/2
__device__ float g_outr[N_MAX];              // out_deg^-1/2
__device__ int   g_cnt[N_MAX];
__device__ int   g_outd[N_MAX];
__device__ int   g_fill[N_MAX];
__device__ int   g_roff[N_MAX + 1];
__device__ int   g_esrc[E_MAX];
__device__ float g_esc[E_MAX];
__device__ int   g_sstate[64];               // lookback scan state

__device__ __half g_featH[(size_t)N_MAX * F];       // fp16(feature)
__device__ __half g_wb[F * NW];                     // [k][n512] = [W_self | W]
__device__ __half g_h0[(size_t)N_MAX * F];          // feature@W_self (fp16)
__device__ __half g_h1[(size_t)N_MAX * F];          // feature@W      (fp16)

// -------- helpers --------
__device__ __forceinline__ uint32_t sptr(const void* p) {
    return (uint32_t)__cvta_generic_to_shared(p);
}
__device__ __forceinline__ void ldsm4(unsigned r[4], uint32_t a) {
    asm volatile("ldmatrix.sync.aligned.m8n8.x4.shared.b16 {%0,%1,%2,%3}, [%4];\n"
        : "=r"(r[0]), "=r"(r[1]), "=r"(r[2]), "=r"(r[3]) : "r"(a));
}
__device__ __forceinline__ void ldsm4t(unsigned r[4], uint32_t a) {
    asm volatile("ldmatrix.sync.aligned.m8n8.x4.trans.shared.b16 {%0,%1,%2,%3}, [%4];\n"
        : "=r"(r[0]), "=r"(r[1]), "=r"(r[2]), "=r"(r[3]) : "r"(a));
}
__device__ __forceinline__ void mma_f16(float* d, const unsigned a[4],
                                        unsigned b0, unsigned b1) {
    asm volatile(
        "mma.sync.aligned.m16n8k16.row.col.f32.f16.f16.f32 "
        "{%0,%1,%2,%3}, {%4,%5,%6,%7}, {%8,%9}, {%0,%1,%2,%3};\n"
        : "+f"(d[0]), "+f"(d[1]), "+f"(d[2]), "+f"(d[3])
        : "r"(a[0]), "r"(a[1]), "r"(a[2]), "r"(a[3]), "r"(b0), "r"(b1));
}
__device__ __forceinline__ void cp16(uint32_t dst, const void* src) {
    asm volatile("cp.async.cg.shared.global [%0], [%1], 16;\n" :: "r"(dst), "l"(src));
}
__device__ __forceinline__ void cp16z(uint32_t dst, const void* src, int sz) {
    asm volatile("cp.async.cg.shared.global [%0], [%1], 16, %2;\n"
                 :: "r"(dst), "l"(src), "r"(sz));
}
__device__ __forceinline__ void cp_commit() {
    asm volatile("cp.async.commit_group;\n" ::: "memory");
}
__device__ __forceinline__ void cp_wait2() {
    asm volatile("cp.async.wait_group 2;\n" ::: "memory");
}
__device__ __forceinline__ void cp_wait0() {
    asm volatile("cp.async.wait_group 0;\n" ::: "memory");
}

// ---------------- fused: hist | convert feature | convert W ----------------
__global__ void phaseA_kernel(const int* __restrict__ src,
                              const int* __restrict__ dst,
                              const float* __restrict__ feat,
                              const float* __restrict__ Ws,
                              const float* __restrict__ Wn,
                              int e, int q, int HB, int CB) {
    int b = blockIdx.x, t = threadIdx.x;
    if (b < HB) {
        int i = b * 256 + t;
        if (i < e) {
            atomicAdd(&g_cnt[dst[i]], 1);
            atomicAdd(&g_outd[src[i]], 1);
        }
    } else if (b < HB + CB) {
        int i = (b - HB) * 256 + t;
        if (i < q) {
            float4 v = ((const float4*)feat)[i];
            __half2 H0 = __floats2half2_rn(v.x, v.y);
            __half2 H1 = __floats2half2_rn(v.z, v.w);
            ((uint2*)g_featH)[i] = make_uint2(*(unsigned*)&H0, *(unsigned*)&H1);
        }
    } else {
        int i = (b - HB - CB) * 256 + t;
        if (i < F * F) {
            int k = i >> 8, nn = i & 255;
            g_wb[k * NW + nn]       = __float2half_rn(Ws[i]);
            g_wb[k * NW + 256 + nn] = __float2half_rn(Wn[i]);
        }
    }
}

// ---------------- single-pass scan (warp-shuffle + decoupled lookback) -----
// Also restores g_cnt/g_outd to zero for the next graph replay.
__global__ void __launch_bounds__(1024)
scan_fused_kernel(int n) {
    __shared__ int warpsum[32];
    __shared__ int s_pre;
    int b = blockIdx.x, t = threadIdx.x;
    int lane = t & 31, w = t >> 5;
    int i = b * 1024 + t;
    int cnt  = (i < n) ? g_cnt[i] : 0;
    int outd = (i < n) ? g_outd[i] : 0;

    int x = cnt;
    #pragma unroll
    for (int off = 1; off < 32; off <<= 1) {
        int y = __shfl_up_sync(0xffffffffu, x, off);
        if (lane >= off) x += y;
    }
    if (lane == 31) warpsum[w] = x;
    __syncthreads();
    if (w == 0) {
        int v = warpsum[lane];
        #pragma unroll
        for (int off = 1; off < 32; off <<= 1) {
            int y = __shfl_up_sync(0xffffffffu, v, off);
            if (lane >= off) v += y;
        }
        warpsum[lane] = v;
    }
    __syncthreads();
    int incl = x + (w ? warpsum[w - 1] : 0);
    int total = warpsum[31];

    if (t == 0) {
        volatile int* st = g_sstate;
        if (b == 0) {
            st[0] = (total << 2) | 2;
            s_pre = 0;
        } else {
            st[b] = (total << 2) | 1;          // publish aggregate
            int pre = 0;
            int j = b - 1;
            while (j >= 0) {
                int v = st[j];
                int f = v & 3;
                if (f == 2) { pre += (v >> 2); break; }
                if (f == 1) { pre += (v >> 2); --j; }
            }
            st[b] = ((total + pre) << 2) | 2;  // upgrade to inclusive
            s_pre = pre;
        }
    }
    __syncthreads();
    int incl_g = incl + s_pre;
    if (i < n) {
        g_roff[i + 1] = incl_g;
        g_fill[i] = incl_g - cnt;
        g_outr[i] = rsqrtf(fmaxf((float)outd, 1.0f));
        g_sin[i]  = rsqrtf(fmaxf((float)cnt, 1.0f));
        g_cnt[i]  = 0;                         // restore zero invariant
        g_outd[i] = 0;
        if (i == 0) g_roff[0] = 0;
    }
}

// ---------------- GEMM (1-term fp16, 4-stage pipeline) + in-CTA fill -------
#define A_STRIDE 40
#define B_STRIDE 136
#define ST_ELEMS 9472            // 128*40 + 32*136
#define AH_OFF(s) ((s) * ST_ELEMS)
#define BH_OFF(s) ((s) * ST_ELEMS + 5120)
#define NSTAGE 4
#define SMEM_DYN (NSTAGE * ST_ELEMS * 2)

__device__ __forceinline__ void load_stage(uint32_t sb, int stage, int it,
                                           int mBase, int nBase, int n, int tid) {
    int k0 = it * 32;
    #pragma unroll
    for (int u = 0; u < 2; ++u) {
        int idx = u * 256 + tid;
        int row = idx >> 2, un = idx & 3;
        int gr = mBase + row;
        int grc = min(gr, n - 1);
        size_t go = (size_t)grc * F + k0 + un * 8;
        int sz = (gr < n) ? 16 : 0;
        uint32_t doff = (uint32_t)(row * A_STRIDE + un * 8) * 2;
        cp16z(sb + (uint32_t)AH_OFF(stage) * 2 + doff, g_featH + go, sz);
    }
    #pragma unroll
    for (int u = 0; u < 2; ++u) {
        int idx = u * 256 + tid;
        int row = idx >> 4, un = idx & 15;
        size_t go = (size_t)(k0 + row) * NW + nBase + un * 8;
        uint32_t doff = (uint32_t)(row * B_STRIDE + un * 8) * 2;
        cp16(sb + (uint32_t)BH_OFF(stage) * 2 + doff, g_wb + go);
    }
}

__global__ void __launch_bounds__(256, 2)
gemmfill_kernel(const int* __restrict__ src,
                const int* __restrict__ dst,
                const float* __restrict__ e_w,
                float* __restrict__ out_tail,
                int n, int e, int EPB) {
    extern __shared__ __align__(128) char smraw[];
    __half* base = (__half*)smraw;
    uint32_t sb = sptr(smraw);

    int b = blockIdx.x, tid = threadIdx.x;
    int wid = tid >> 5, lane = tid & 31;
    int wm = wid & 3, wn = wid >> 2;
    int t = b;
    int mBase = (t >> 2) * 128;
    int tn = t & 3;
    int nBase = tn * 128;

    float acc[2][8][4];
    #pragma unroll
    for (int i = 0; i < 2; ++i)
        #pragma unroll
        for (int j = 0; j < 8; ++j)
            #pragma unroll
            for (int q = 0; q < 4; ++q) acc[i][j][q] = 0.f;

    load_stage(sb, 0, 0, mBase, nBase, n, tid); cp_commit();
    load_stage(sb, 1, 1, mBase, nBase, n, tid); cp_commit();
    load_stage(sb, 2, 2, mBase, nBase, n, tid); cp_commit();

    #pragma unroll 1
    for (int it = 0; it < 8; ++it) {
        if (it < 6) cp_wait2(); else cp_wait0();
        __syncthreads();
        if (it + 3 < 8) {
            load_stage(sb, (it + 3) % NSTAGE, it + 3, mBase, nBase, n, tid);
            cp_commit();
        }
        int st = it % NSTAGE;
        #pragma unroll
        for (int kt = 0; kt < 2; ++kt) {
            int ks = kt * 16;
            unsigned aH[2][4];
            #pragma unroll
            for (int mt = 0; mt < 2; ++mt) {
                int r = wm * 32 + mt * 16 + (lane & 15);
                int c = ks + (lane >> 4) * 8;
                ldsm4(aH[mt], sptr(base + AH_OFF(st) + r * A_STRIDE + c));
            }
            #pragma unroll
            for (int nc = 0; nc < 4; ++nc) {
                int rB = ks + (lane & 15);
                int cB = wn * 64 + nc * 16 + (lane >> 4) * 8;
                unsigned bH[4];
                ldsm4t(bH, sptr(base + BH_OFF(st) + rB * B_STRIDE + cB));
                #pragma unroll
                for (int mt = 0; mt < 2; ++mt) {
                    mma_f16(acc[mt][nc * 2],     aH[mt], bH[0], bH[1]);
                    mma_f16(acc[mt][nc * 2 + 1], aH[mt], bH[2], bH[3]);
                }
            }
        }
    }

    // epilogue: fp16 to g_h0 (tn<2) or g_h1 (tn>=2)
    __half* dstp = (tn < 2) ? g_h0 : g_h1;
    #pragma unroll
    for (int mt = 0; mt < 2; ++mt) {
        int r0 = mBase + wm * 32 + mt * 16 + (lane >> 2);
        int r1 = r0 + 8;
        #pragma unroll
        for (int nt = 0; nt < 8; ++nt) {
            int cl = wn * 64 + nt * 8 + (lane & 3) * 2;
            int c = (tn & 1) * 128 + cl;
            float* d = acc[mt][nt];
            if (r0 < n) {
                __half2 v = __floats2half2_rn(d[0], d[1]);
                *(unsigned*)(dstp + (size_t)r0 * F + c) = *(unsigned*)&v;
            }
            if (r1 < n) {
                __half2 v = __floats2half2_rn(d[2], d[3]);
                *(unsigned*)(dstp + (size_t)r1 * F + c) = *(unsigned*)&v;
            }
        }
    }

    // ----- CSR fill: this CTA's edge slice (no extra residency cost) -----
    if (b == 0 && tid < 64) g_sstate[tid] = 0;   // restore for next replay
    int e0 = b * EPB;
    #pragma unroll 2
    for (int i = e0 + tid; i < min(e0 + EPB, e); i += 256) {
        float w = e_w[i];
        int s = src[i];
        int p = atomicAdd(&g_fill[dst[i]], 1);
        g_esrc[p] = s;
        g_esc[p] = w * g_outr[s];
        out_tail[i] = w;                 // e_w passthrough output
    }
}

// ---------------- final: out = h0 + si*(S . h1) + si*b (MLP=8 gather) ------
__global__ void __launch_bounds__(256)
final_kernel(const float* __restrict__ bias, float* __restrict__ out, int n) {
    int row  = blockIdx.x * 8 + (threadIdx.x >> 5);
    int lane = threadIdx.x & 31;
    if (row >= n) return;
    int beg = g_roff[row], end = g_roff[row + 1];
    float a[8];
    #pragma unroll
    for (int j = 0; j < 8; ++j) a[j] = 0.f;

    for (int base = beg; base < end; base += 32) {
        int m = min(32, end - base);
        int sE = 0; float cE = 0.f;
        if (lane < m) { sE = g_esrc[base + lane]; cE = g_esc[base + lane]; }
        int j = 0;
        for (; j + 8 <= m; j += 8) {
            uint4 d[8];
            #pragma unroll
            for (int u = 0; u < 8; ++u) {
                int ss = __shfl_sync(0xffffffffu, sE, j + u);
                d[u] = *(const uint4*)(g_h1 + (size_t)ss * F + lane * 8);
            }
            #pragma unroll
            for (int u = 0; u < 8; ++u) {
                float sc = __shfl_sync(0xffffffffu, cE, j + u);
                float2 f0 = __half22float2(*(__half2*)&d[u].x);
                float2 f1 = __half22float2(*(__half2*)&d[u].y);
                float2 f2 = __half22float2(*(__half2*)&d[u].z);
                float2 f3 = __half22float2(*(__half2*)&d[u].w);
                a[0] += f0.x * sc; a[1] += f0.y * sc;
                a[2] += f1.x * sc; a[3] += f1.y * sc;
                a[4] += f2.x * sc; a[5] += f2.y * sc;
                a[6] += f3.x * sc; a[7] += f3.y * sc;
            }
        }
        for (; j < m; ++j) {
            int   ss = __shfl_sync(0xffffffffu, sE, j);
            float sc = __shfl_sync(0xffffffffu, cE, j);
            uint4 d = *(const uint4*)(g_h1 + (size_t)ss * F + lane * 8);
            float2 f0 = __half22float2(*(__half2*)&d.x);
            float2 f1 = __half22float2(*(__half2*)&d.y);
            float2 f2 = __half22float2(*(__half2*)&d.z);
            float2 f3 = __half22float2(*(__half2*)&d.w);
            a[0] += f0.x * sc; a[1] += f0.y * sc;
            a[2] += f1.x * sc; a[3] += f1.y * sc;
            a[4] += f2.x * sc; a[5] += f2.y * sc;
            a[6] += f3.x * sc; a[7] += f3.y * sc;
        }
    }

    float si = g_sin[row];
    uint4 h = *(const uint4*)(g_h0 + (size_t)row * F + lane * 8);
    float2 s0 = __half22float2(*(__half2*)&h.x);
    float2 s1 = __half22float2(*(__half2*)&h.y);
    float2 s2 = __half22float2(*(__half2*)&h.z);
    float2 s3 = __half22float2(*(__half2*)&h.w);
    float4 b0 = *(const float4*)(bias + lane * 8);
    float4 b1 = *(const float4*)(bias + lane * 8 + 4);
    float4 o0, o1;
    o0.x = s0.x + si * (a[0] + b0.x); o0.y = s0.y + si * (a[1] + b0.y);
    o0.z = s1.x + si * (a[2] + b0.z); o0.w = s1.y + si * (a[3] + b0.w);
    o1.x = s2.x + si * (a[4] + b1.x); o1.y = s2.y + si * (a[5] + b1.y);
    o1.z = s3.x + si * (a[6] + b1.z); o1.w = s3.y + si * (a[7] + b1.w);
    float* op = out + (size_t)row * F + lane * 8;
    *(float4*)(op)     = o0;
    *(float4*)(op + 4) = o1;
}

// ---------------- launch ----------------
extern "C" void kernel_launch(void* const* d_in, const int* in_sizes, int n_in,
                              void* d_out, int out_size) {
    const float* feature = (const float*)d_in[0];
    const float* e_w     = (const float*)d_in[1];
    const float* W_self  = (const float*)d_in[4];
    const float* W       = (const float*)d_in[5];
    const float* b       = (const float*)d_in[6];
    const int*   src     = (const int*)d_in[7];
    const int*   dst     = (const int*)d_in[8];
    float*       out     = (float*)d_out;

    int n = in_sizes[0] / F;
    int e = in_sizes[1];
    int q = n * (F / 4);

    static bool init = false;
    if (!init) {
        cudaFuncSetAttribute(gemmfill_kernel,
                             cudaFuncAttributeMaxDynamicSharedMemorySize, SMEM_DYN);
        init = true;
    }

    // K1: fused hist | convert feature | convert W
    int HB = (e + 255) / 256;
    int CB = (q + 255) / 256;
    int WB = (F * F + 255) / 256;
    phaseA_kernel<<<HB + CB + WB, 256>>>(src, dst, feature, W_self, W,
                                         e, q, HB, CB);

    // K2: single-pass scan (+ restores count buffers to zero)
    int NB = (n + 1023) / 1024;     // <= 64
    scan_fused_kernel<<<NB, 1024>>>(n);

    // K3: GEMM (1-term fp16, 4-stage); each CTA fills its edge slice after
    int NT = ((n + 127) / 128) * 4;
    int EPB = (e + NT - 1) / NT;
    gemmfill_kernel<<<NT, 256, SMEM_DYN>>>(src, dst, e_w,
                                           out + (size_t)n * F, n, e, EPB);

    // K4: final gather + epilogue (MLP=8)
    final_kernel<<<(n + 7) / 8, 256>>>(b, out, n);
}

// round 13
// speedup vs baseline: 1.2305x; 1.0073x over previous
#include <cuda_runtime.h>
#include <cuda_bf16.h>
#include <cuda_fp16.h>
#include <math.h>
#include <stdint.h>

#define F 256
#define NW 512           // fused B width: [W_self | W]
#define N_MAX 50048
#define E_MAX 800256

// -------- device scratch (zero-initialized at module load; replay invariants:
// scan role restores g_cnt/g_outd/g_rowctr; final restores g_sstate/g_done_ctr)
__device__ float g_sin[N_MAX];               // in_deg^-1/2
__device__ float g_outr[N_MAX];              // out_deg^-1/2
__device__ int   g_cnt[N_MAX];
__device__ int   g_outd[N_MAX];
__device__ int   g_fill[N_MAX];
__device__ int   g_roff[N_MAX + 1];
__device__ int   g_esrc[E_MAX];
__device__ float g_esc[E_MAX];
__device__ int   g_sstate[64];               // lookback scan state
__device__ int   g_done_ctr;                 // scan-complete counter
__device__ int   g_rowctr;                   // dynamic row queue for final

__device__ __half g_featH[(size_t)N_MAX * F];       // fp16(feature)
__device__ __half g_wb[F * NW];                     // [k][n512] = [W_self | W]
__device__ __half g_h0[(size_t)N_MAX * F];          // feature@W_self (fp16)
__device__ __half g_h1[(size_t)N_MAX * F];          // feature@W      (fp16)

// -------- helpers --------
__device__ __forceinline__ uint32_t sptr(const void* p) {
    return (uint32_t)__cvta_generic_to_shared(p);
}
__device__ __forceinline__ void ldsm4(unsigned r[4], uint32_t a) {
    asm volatile("ldmatrix.sync.aligned.m8n8.x4.shared.b16 {%0,%1,%2,%3}, [%4];\n"
        : "=r"(r[0]), "=r"(r[1]), "=r"(r[2]), "=r"(r[3]) : "r"(a));
}
__device__ __forceinline__ void ldsm4t(unsigned r[4], uint32_t a) {
    asm volatile("ldmatrix.sync.aligned.m8n8.x4.trans.shared.b16 {%0,%1,%2,%3}, [%4];\n"
        : "=r"(r[0]), "=r"(r[1]), "=r"(r[2]), "=r"(r[3]) : "r"(a));
}
__device__ __forceinline__ void mma_f16(float* d, const unsigned a[4],
                                        unsigned b0, unsigned b1) {
    asm volatile(
        "mma.sync.aligned.m16n8k16.row.col.f32.f16.f16.f32 "
        "{%0,%1,%2,%3}, {%4,%5,%6,%7}, {%8,%9}, {%0,%1,%2,%3};\n"
        : "+f"(d[0]), "+f"(d[1]), "+f"(d[2]), "+f"(d[3])
        : "r"(a[0]), "r"(a[1]), "r"(a[2]), "r"(a[3]), "r"(b0), "r"(b1));
}
__device__ __forceinline__ void cp16(uint32_t dst, const void* src) {
    asm volatile("cp.async.cg.shared.global [%0], [%1], 16;\n" :: "r"(dst), "l"(src));
}
__device__ __forceinline__ void cp16z(uint32_t dst, const void* src, int sz) {
    asm volatile("cp.async.cg.shared.global [%0], [%1], 16, %2;\n"
                 :: "r"(dst), "l"(src), "r"(sz));
}
__device__ __forceinline__ void cp_commit() {
    asm volatile("cp.async.commit_group;\n" ::: "memory");
}
__device__ __forceinline__ void cp_wait2() {
    asm volatile("cp.async.wait_group 2;\n" ::: "memory");
}
__device__ __forceinline__ void cp_wait0() {
    asm volatile("cp.async.wait_group 0;\n" ::: "memory");
}

// ---------------- fused: hist | convert feature | convert W ----------------
__global__ void phaseA_kernel(const int* __restrict__ src,
                              const int* __restrict__ dst,
                              const float* __restrict__ feat,
                              const float* __restrict__ Ws,
                              const float* __restrict__ Wn,
                              int e, int q, int HB, int CB) {
    int b = blockIdx.x, t = threadIdx.x;
    if (b < HB) {
        int i = b * 256 + t;
        if (i < e) {
            atomicAdd(&g_cnt[dst[i]], 1);
            atomicAdd(&g_outd[src[i]], 1);
        }
    } else if (b < HB + CB) {
        int i = (b - HB) * 256 + t;
        if (i < q) {
            float4 v = ((const float4*)feat)[i];
            __half2 H0 = __floats2half2_rn(v.x, v.y);
            __half2 H1 = __floats2half2_rn(v.z, v.w);
            ((uint2*)g_featH)[i] = make_uint2(*(unsigned*)&H0, *(unsigned*)&H1);
        }
    } else {
        int i = (b - HB - CB) * 256 + t;
        if (i < F * F) {
            int k = i >> 8, nn = i & 255;
            g_wb[k * NW + nn]       = __float2half_rn(Ws[i]);
            g_wb[k * NW + 256 + nn] = __float2half_rn(Wn[i]);
        }
    }
}

// ---------------- GEMM + embedded scan + in-CTA fill ----------------------
// Blocks [0, NB): scan role (warp-shuffle scan + decoupled lookback over
//   1024 counts each; all NB<=64 blocks land in wave 1, spin-safe).
// Blocks [NB, NB+NT): 128x128 GEMM tile; after epilogue each CTA scatters
//   its edge slice (gated on scan completion via fenced counter).
#define A_STRIDE 40
#define B_STRIDE 136
#define ST_ELEMS 9472            // 128*40 + 32*136
#define AH_OFF(s) ((s) * ST_ELEMS)
#define BH_OFF(s) ((s) * ST_ELEMS + 5120)
#define NSTAGE 4
#define SMEM_DYN (NSTAGE * ST_ELEMS * 2)

__device__ __forceinline__ void load_stage(uint32_t sb, int stage, int it,
                                           int mBase, int nBase, int n, int tid) {
    int k0 = it * 32;
    #pragma unroll
    for (int u = 0; u < 2; ++u) {
        int idx = u * 256 + tid;
        int row = idx >> 2, un = idx & 3;
        int gr = mBase + row;
        int grc = min(gr, n - 1);
        size_t go = (size_t)grc * F + k0 + un * 8;
        int sz = (gr < n) ? 16 : 0;
        uint32_t doff = (uint32_t)(row * A_STRIDE + un * 8) * 2;
        cp16z(sb + (uint32_t)AH_OFF(stage) * 2 + doff, g_featH + go, sz);
    }
    #pragma unroll
    for (int u = 0; u < 2; ++u) {
        int idx = u * 256 + tid;
        int row = idx >> 4, un = idx & 15;
        size_t go = (size_t)(k0 + row) * NW + nBase + un * 8;
        uint32_t doff = (uint32_t)(row * B_STRIDE + un * 8) * 2;
        cp16(sb + (uint32_t)BH_OFF(stage) * 2 + doff, g_wb + go);
    }
}

__global__ void __launch_bounds__(256, 2)
gemmfill_kernel(const int* __restrict__ src,
                const int* __restrict__ dst,
                const float* __restrict__ e_w,
                float* __restrict__ out_tail,
                int n, int e, int EPB, int NB) {
    int b = blockIdx.x, tid = threadIdx.x;

    // =================== scan role ===================
    if (b < NB) {
        __shared__ int warpsum[8];
        __shared__ int s_pre;
        int lane = tid & 31, w = tid >> 5;
        if (b == 0 && tid == 0) g_rowctr = 0;   // reset row queue for final
        int base = b * 1024 + tid * 4;
        int c[4], o[4];
        #pragma unroll
        for (int j = 0; j < 4; ++j) {
            int idx = base + j;
            c[j] = (idx < n) ? g_cnt[idx] : 0;
            o[j] = (idx < n) ? g_outd[idx] : 0;
        }
        int s1 = c[0], s2 = s1 + c[1], s3 = s2 + c[2], s4 = s3 + c[3];
        int x = s4;
        #pragma unroll
        for (int off = 1; off < 32; off <<= 1) {
            int y = __shfl_up_sync(0xffffffffu, x, off);
            if (lane >= off) x += y;
        }
        if (lane == 31) warpsum[w] = x;
        __syncthreads();
        if (w == 0 && lane < 8) {
            int v = warpsum[lane];
            #pragma unroll
            for (int off = 1; off < 8; off <<= 1) {
                int y = __shfl_up_sync(0xffu, v, off);
                if (lane >= off) v += y;
            }
            warpsum[lane] = v;
        }
        __syncthreads();
        int texcl = x - s4 + (w ? warpsum[w - 1] : 0);
        int total = warpsum[7];

        if (tid == 0) {
            volatile int* st = g_sstate;
            if (b == 0) {
                st[0] = (total << 2) | 2;
                s_pre = 0;
            } else {
                st[b] = (total << 2) | 1;          // publish aggregate
                int pre = 0;
                int j = b - 1;
                while (j >= 0) {
                    int v = st[j];
                    int f = v & 3;
                    if (f == 2) { pre += (v >> 2); break; }
                    if (f == 1) { pre += (v >> 2); --j; }
                }
                st[b] = ((total + pre) << 2) | 2;  // upgrade to inclusive
                s_pre = pre;
            }
        }
        __syncthreads();
        int e0 = texcl + s_pre;
        int sj[4] = {s1, s2, s3, s4};
        #pragma unroll
        for (int j = 0; j < 4; ++j) {
            int idx = base + j;
            if (idx < n) {
                g_roff[idx + 1] = e0 + sj[j];
                g_fill[idx] = e0 + (j ? sj[j - 1] : 0);
                g_outr[idx] = rsqrtf(fmaxf((float)o[j], 1.0f));
                g_sin[idx]  = rsqrtf(fmaxf((float)c[j], 1.0f));
                g_cnt[idx]  = 0;                   // restore zero invariant
                g_outd[idx] = 0;
            }
        }
        if (b == 0 && tid == 0) g_roff[0] = 0;
        __threadfence();
        __syncthreads();
        if (tid == 0) atomicAdd(&g_done_ctr, 1);
        return;
    }

    // =================== GEMM role ===================
    extern __shared__ __align__(128) char smraw[];
    __half* base = (__half*)smraw;
    uint32_t sb = sptr(smraw);

    int wid = tid >> 5, lane = tid & 31;
    int wm = wid & 3, wn = wid >> 2;
    int t = b - NB;
    int mBase = (t >> 2) * 128;
    int tn = t & 3;
    int nBase = tn * 128;

    float acc[2][8][4];
    #pragma unroll
    for (int i = 0; i < 2; ++i)
        #pragma unroll
        for (int j = 0; j < 8; ++j)
            #pragma unroll
            for (int q = 0; q < 4; ++q) acc[i][j][q] = 0.f;

    load_stage(sb, 0, 0, mBase, nBase, n, tid); cp_commit();
    load_stage(sb, 1, 1, mBase, nBase, n, tid); cp_commit();
    load_stage(sb, 2, 2, mBase, nBase, n, tid); cp_commit();

    #pragma unroll 1
    for (int it = 0; it < 8; ++it) {
        if (it < 6) cp_wait2(); else cp_wait0();
        __syncthreads();
        if (it + 3 < 8) {
            load_stage(sb, (it + 3) % NSTAGE, it + 3, mBase, nBase, n, tid);
            cp_commit();
        }
        int st = it % NSTAGE;
        #pragma unroll
        for (int kt = 0; kt < 2; ++kt) {
            int ks = kt * 16;
            unsigned aH[2][4];
            #pragma unroll
            for (int mt = 0; mt < 2; ++mt) {
                int r = wm * 32 + mt * 16 + (lane & 15);
                int c = ks + (lane >> 4) * 8;
                ldsm4(aH[mt], sptr(base + AH_OFF(st) + r * A_STRIDE + c));
            }
            #pragma unroll
            for (int nc = 0; nc < 4; ++nc) {
                int rB = ks + (lane & 15);
                int cB = wn * 64 + nc * 16 + (lane >> 4) * 8;
                unsigned bH[4];
                ldsm4t(bH, sptr(base + BH_OFF(st) + rB * B_STRIDE + cB));
                #pragma unroll
                for (int mt = 0; mt < 2; ++mt) {
                    mma_f16(acc[mt][nc * 2],     aH[mt], bH[0], bH[1]);
                    mma_f16(acc[mt][nc * 2 + 1], aH[mt], bH[2], bH[3]);
                }
            }
        }
    }

    // epilogue: fp16 to g_h0 (tn<2) or g_h1 (tn>=2)
    __half* dstp = (tn < 2) ? g_h0 : g_h1;
    #pragma unroll
    for (int mt = 0; mt < 2; ++mt) {
        int r0 = mBase + wm * 32 + mt * 16 + (lane >> 2);
        int r1 = r0 + 8;
        #pragma unroll
        for (int nt = 0; nt < 8; ++nt) {
            int cl = wn * 64 + nt * 8 + (lane & 3) * 2;
            int c = (tn & 1) * 128 + cl;
            float* d = acc[mt][nt];
            if (r0 < n) {
                __half2 v = __floats2half2_rn(d[0], d[1]);
                *(unsigned*)(dstp + (size_t)r0 * F + c) = *(unsigned*)&v;
            }
            if (r1 < n) {
                __half2 v = __floats2half2_rn(d[2], d[3]);
                *(unsigned*)(dstp + (size_t)r1 * F + c) = *(unsigned*)&v;
            }
        }
    }

    // ----- CSR fill (gated on scan completion) -----
    if (tid == 0) {
        while (*((volatile int*)&g_done_ctr) < NB) __nanosleep(128);
    }
    __syncthreads();
    __threadfence();
    int e0 = t * EPB;
    #pragma unroll 2
    for (int i = e0 + tid; i < min(e0 + EPB, e); i += 256) {
        float w = e_w[i];
        int s = src[i];
        int p = atomicAdd(&g_fill[dst[i]], 1);
        g_esrc[p] = s;
        g_esc[p] = w * g_outr[s];
        out_tail[i] = w;                 // e_w passthrough output
    }
}

// ---------------- final: persistent, dynamic row queue ---------------------
// out = h0 + si*(S . h1) + si*b; warp grabs 2 rows at a time (MLP=8 gather).
__global__ void __launch_bounds__(256)
final_kernel(const float* __restrict__ bias, float* __restrict__ out, int n) {
    if (blockIdx.x == 0) {
        if (threadIdx.x == 0) g_done_ctr = 0;        // restore for next replay
        if (threadIdx.x < 64) g_sstate[threadIdx.x] = 0;
    }
    int lane = threadIdx.x & 31;

    while (true) {
        int r0 = 0;
        if (lane == 0) r0 = atomicAdd(&g_rowctr, 2);
        r0 = __shfl_sync(0xffffffffu, r0, 0);
        if (r0 >= n) break;
        int rend = min(r0 + 2, n);

        for (int row = r0; row < rend; ++row) {
            int beg = g_roff[row], end = g_roff[row + 1];
            float a[8];
            #pragma unroll
            for (int j = 0; j < 8; ++j) a[j] = 0.f;

            for (int base = beg; base < end; base += 32) {
                int m = min(32, end - base);
                int sE = 0; float cE = 0.f;
                if (lane < m) { sE = g_esrc[base + lane]; cE = g_esc[base + lane]; }
                int j = 0;
                for (; j + 8 <= m; j += 8) {
                    uint4 d[8];
                    #pragma unroll
                    for (int u = 0; u < 8; ++u) {
                        int ss = __shfl_sync(0xffffffffu, sE, j + u);
                        d[u] = *(const uint4*)(g_h1 + (size_t)ss * F + lane * 8);
                    }
                    #pragma unroll
                    for (int u = 0; u < 8; ++u) {
                        float sc = __shfl_sync(0xffffffffu, cE, j + u);
                        float2 f0 = __half22float2(*(__half2*)&d[u].x);
                        float2 f1 = __half22float2(*(__half2*)&d[u].y);
                        float2 f2 = __half22float2(*(__half2*)&d[u].z);
                        float2 f3 = __half22float2(*(__half2*)&d[u].w);
                        a[0] += f0.x * sc; a[1] += f0.y * sc;
                        a[2] += f1.x * sc; a[3] += f1.y * sc;
                        a[4] += f2.x * sc; a[5] += f2.y * sc;
                        a[6] += f3.x * sc; a[7] += f3.y * sc;
                    }
                }
                for (; j < m; ++j) {
                    int   ss = __shfl_sync(0xffffffffu, sE, j);
                    float sc = __shfl_sync(0xffffffffu, cE, j);
                    uint4 d = *(const uint4*)(g_h1 + (size_t)ss * F + lane * 8);
                    float2 f0 = __half22float2(*(__half2*)&d.x);
                    float2 f1 = __half22float2(*(__half2*)&d.y);
                    float2 f2 = __half22float2(*(__half2*)&d.z);
                    float2 f3 = __half22float2(*(__half2*)&d.w);
                    a[0] += f0.x * sc; a[1] += f0.y * sc;
                    a[2] += f1.x * sc; a[3] += f1.y * sc;
                    a[4] += f2.x * sc; a[5] += f2.y * sc;
                    a[6] += f3.x * sc; a[7] += f3.y * sc;
                }
            }

            float si = g_sin[row];
            uint4 h = *(const uint4*)(g_h0 + (size_t)row * F + lane * 8);
            float2 s0 = __half22float2(*(__half2*)&h.x);
            float2 s1 = __half22float2(*(__half2*)&h.y);
            float2 s2 = __half22float2(*(__half2*)&h.z);
            float2 s3 = __half22float2(*(__half2*)&h.w);
            float4 b0 = *(const float4*)(bias + lane * 8);
            float4 b1 = *(const float4*)(bias + lane * 8 + 4);
            float4 o0, o1;
            o0.x = s0.x + si * (a[0] + b0.x); o0.y = s0.y + si * (a[1] + b0.y);
            o0.z = s1.x + si * (a[2] + b0.z); o0.w = s1.y + si * (a[3] + b0.w);
            o1.x = s2.x + si * (a[4] + b1.x); o1.y = s2.y + si * (a[5] + b1.y);
            o1.z = s3.x + si * (a[6] + b1.z); o1.w = s3.y + si * (a[7] + b1.w);
            float* op = out + (size_t)row * F + lane * 8;
            *(float4*)(op)     = o0;
            *(float4*)(op + 4) = o1;
        }
    }
}

// ---------------- launch ----------------
extern "C" void kernel_launch(void* const* d_in, const int* in_sizes, int n_in,
                              void* d_out, int out_size) {
    const float* feature = (const float*)d_in[0];
    const float* e_w     = (const float*)d_in[1];
    const float* W_self  = (const float*)d_in[4];
    const float* W       = (const float*)d_in[5];
    const float* b       = (const float*)d_in[6];
    const int*   src     = (const int*)d_in[7];
    const int*   dst     = (const int*)d_in[8];
    float*       out     = (float*)d_out;

    int n = in_sizes[0] / F;
    int e = in_sizes[1];
    int q = n * (F / 4);

    static bool init = false;
    if (!init) {
        cudaFuncSetAttribute(gemmfill_kernel,
                             cudaFuncAttributeMaxDynamicSharedMemorySize, SMEM_DYN);
        init = true;
    }

    // K1: fused hist | convert feature | convert W
    int HB = (e + 255) / 256;
    int CB = (q + 255) / 256;
    int WB = (F * F + 255) / 256;
    phaseA_kernel<<<HB + CB + WB, 256>>>(src, dst, feature, W_self, W,
                                         e, q, HB, CB);

    // K2: scan blocks + GEMM tiles + gated CSR fill, one launch
    int NB = (n + 1023) / 1024;          // <= 64 (scan role blocks)
    int NT = ((n + 127) / 128) * 4;      // gemm tiles
    int EPB = (e + NT - 1) / NT;
    gemmfill_kernel<<<NB + NT, 256, SMEM_DYN>>>(src, dst, e_w,
                                                out + (size_t)n * F,
                                                n, e, EPB, NB);

    // K3: final gather + epilogue (persistent, dynamic row queue)
    final_kernel<<<740, 256>>>(b, out, n);
}

// round 14
// speedup vs baseline: 1.2358x; 1.0043x over previous
#include <cuda_runtime.h>
#include <cuda_bf16.h>
#include <cuda_fp16.h>
#include <math.h>
#include <stdint.h>

#define F 256
#define NW 512           // fused B width: [W_self | W]
#define N_MAX 50048
#define E_MAX 800256
#define EPC 2048         // edges per fill chunk

// -------- device scratch (zero-initialized at module load; replay invariants:
// scan role restores g_cnt/g_outd/g_rowctr; final restores the rest) --------
__device__ float g_sin[N_MAX];               // in_deg^-1/2
__device__ float g_outr[N_MAX];              // out_deg^-1/2
__device__ int   g_cnt[N_MAX];
__device__ int   g_outd[N_MAX];
__device__ int   g_fill[N_MAX];
__device__ int   g_roff[N_MAX + 1];
__device__ int   g_esrc[E_MAX];
__device__ float g_esc[E_MAX];
__device__ int   g_sstate[64];               // lookback scan state
__device__ int   g_done_ctr;                 // scan-complete counter
__device__ int   g_rowctr;                   // dynamic row queue (final)
__device__ int   g_tilectr;                  // dynamic tile queue (gemm)
__device__ int   g_edgectr;                  // dynamic edge-chunk queue (fill)

__device__ __half g_featH[(size_t)N_MAX * F];       // fp16(feature)
__device__ __half g_wb[F * NW];                     // [k][n512] = [W_self | W]
__device__ __half g_h0[(size_t)N_MAX * F];          // feature@W_self (fp16)
__device__ __half g_h1[(size_t)N_MAX * F];          // feature@W      (fp16)

// -------- helpers --------
__device__ __forceinline__ uint32_t sptr(const void* p) {
    return (uint32_t)__cvta_generic_to_shared(p);
}
__device__ __forceinline__ void ldsm4(unsigned r[4], uint32_t a) {
    asm volatile("ldmatrix.sync.aligned.m8n8.x4.shared.b16 {%0,%1,%2,%3}, [%4];\n"
        : "=r"(r[0]), "=r"(r[1]), "=r"(r[2]), "=r"(r[3]) : "r"(a));
}
__device__ __forceinline__ void ldsm4t(unsigned r[4], uint32_t a) {
    asm volatile("ldmatrix.sync.aligned.m8n8.x4.trans.shared.b16 {%0,%1,%2,%3}, [%4];\n"
        : "=r"(r[0]), "=r"(r[1]), "=r"(r[2]), "=r"(r[3]) : "r"(a));
}
__device__ __forceinline__ void mma_f16(float* d, const unsigned a[4],
                                        unsigned b0, unsigned b1) {
    asm volatile(
        "mma.sync.aligned.m16n8k16.row.col.f32.f16.f16.f32 "
        "{%0,%1,%2,%3}, {%4,%5,%6,%7}, {%8,%9}, {%0,%1,%2,%3};\n"
        : "+f"(d[0]), "+f"(d[1]), "+f"(d[2]), "+f"(d[3])
        : "r"(a[0]), "r"(a[1]), "r"(a[2]), "r"(a[3]), "r"(b0), "r"(b1));
}
__device__ __forceinline__ void cp16(uint32_t dst, const void* src) {
    asm volatile("cp.async.cg.shared.global [%0], [%1], 16;\n" :: "r"(dst), "l"(src));
}
__device__ __forceinline__ void cp16z(uint32_t dst, const void* src, int sz) {
    asm volatile("cp.async.cg.shared.global [%0], [%1], 16, %2;\n"
                 :: "r"(dst), "l"(src), "r"(sz));
}
__device__ __forceinline__ void cp_commit() {
    asm volatile("cp.async.commit_group;\n" ::: "memory");
}
__device__ __forceinline__ void cp_wait2() {
    asm volatile("cp.async.wait_group 2;\n" ::: "memory");
}
__device__ __forceinline__ void cp_wait1() {
    asm volatile("cp.async.wait_group 1;\n" ::: "memory");
}
__device__ __forceinline__ void cp_wait0() {
    asm volatile("cp.async.wait_group 0;\n" ::: "memory");
}

// ---------------- fused: hist | convert feature | convert W (MLP=4) --------
__global__ void phaseA_kernel(const int* __restrict__ src,
                              const int* __restrict__ dst,
                              const float* __restrict__ feat,
                              const float* __restrict__ Ws,
                              const float* __restrict__ Wn,
                              int e, int q, int HB, int CB) {
    int b = blockIdx.x, t = threadIdx.x;
    if (b < HB) {
        int base = b * 1024 + t;
        int d[4], s[4];
        #pragma unroll
        for (int u = 0; u < 4; ++u) {
            int i = base + u * 256;
            if (i < e) { d[u] = dst[i]; s[u] = src[i]; } else { d[u] = -1; }
        }
        #pragma unroll
        for (int u = 0; u < 4; ++u) {
            if (d[u] >= 0) {
                atomicAdd(&g_cnt[d[u]], 1);
                atomicAdd(&g_outd[s[u]], 1);
            }
        }
    } else if (b < HB + CB) {
        int base = (b - HB) * 1024 + t;
        float4 v[4];
        #pragma unroll
        for (int u = 0; u < 4; ++u) {
            int i = base + u * 256;
            if (i < q) v[u] = ((const float4*)feat)[i];
        }
        #pragma unroll
        for (int u = 0; u < 4; ++u) {
            int i = base + u * 256;
            if (i < q) {
                __half2 H0 = __floats2half2_rn(v[u].x, v[u].y);
                __half2 H1 = __floats2half2_rn(v[u].z, v[u].w);
                ((uint2*)g_featH)[i] = make_uint2(*(unsigned*)&H0, *(unsigned*)&H1);
            }
        }
    } else {
        int i = (b - HB - CB) * 256 + t;
        if (i < F * F) {
            int k = i >> 8, nn = i & 255;
            g_wb[k * NW + nn]       = __float2half_rn(Ws[i]);
            g_wb[k * NW + 256 + nn] = __float2half_rn(Wn[i]);
        }
    }
}

// ---------------- persistent GEMM + embedded scan + dynamic fill ----------
#define A_STRIDE 40
#define B_STRIDE 136
#define ST_ELEMS 9472            // 128*40 + 32*136
#define AH_OFF(s) ((s) * ST_ELEMS)
#define BH_OFF(s) ((s) * ST_ELEMS + 5120)
#define NSTAGE 4
#define SMEM_DYN (NSTAGE * ST_ELEMS * 2)

__device__ __forceinline__ void load_stage(uint32_t sb, int stage, int kc,
                                           int mBase, int nBase, int n, int tid) {
    int k0 = kc * 32;
    #pragma unroll
    for (int u = 0; u < 2; ++u) {
        int idx = u * 256 + tid;
        int row = idx >> 2, un = idx & 3;
        int gr = mBase + row;
        int grc = min(gr, n - 1);
        size_t go = (size_t)grc * F + k0 + un * 8;
        int sz = (gr < n) ? 16 : 0;
        uint32_t doff = (uint32_t)(row * A_STRIDE + un * 8) * 2;
        cp16z(sb + (uint32_t)AH_OFF(stage) * 2 + doff, g_featH + go, sz);
    }
    #pragma unroll
    for (int u = 0; u < 2; ++u) {
        int idx = u * 256 + tid;
        int row = idx >> 4, un = idx & 15;
        size_t go = (size_t)(k0 + row) * NW + nBase + un * 8;
        uint32_t doff = (uint32_t)(row * B_STRIDE + un * 8) * 2;
        cp16(sb + (uint32_t)BH_OFF(stage) * 2 + doff, g_wb + go);
    }
}

__global__ void __launch_bounds__(256, 2)
gemmfill_kernel(const int* __restrict__ src,
                const int* __restrict__ dst,
                const float* __restrict__ e_w,
                float* __restrict__ out_tail,
                int n, int e, int NT, int NB) {
    int b = blockIdx.x, tid = threadIdx.x;

    // =================== scan role (blocks [0, NB)) ===================
    if (b < NB) {
        __shared__ int warpsum[8];
        __shared__ int s_pre;
        int lane = tid & 31, w = tid >> 5;
        if (b == 0 && tid == 0) g_rowctr = 0;   // reset row queue for final
        int base = b * 1024 + tid * 4;
        int c[4], o[4];
        #pragma unroll
        for (int j = 0; j < 4; ++j) {
            int idx = base + j;
            c[j] = (idx < n) ? g_cnt[idx] : 0;
            o[j] = (idx < n) ? g_outd[idx] : 0;
        }
        int s1 = c[0], s2 = s1 + c[1], s3 = s2 + c[2], s4 = s3 + c[3];
        int x = s4;
        #pragma unroll
        for (int off = 1; off < 32; off <<= 1) {
            int y = __shfl_up_sync(0xffffffffu, x, off);
            if (lane >= off) x += y;
        }
        if (lane == 31) warpsum[w] = x;
        __syncthreads();
        if (w == 0 && lane < 8) {
            int v = warpsum[lane];
            #pragma unroll
            for (int off = 1; off < 8; off <<= 1) {
                int y = __shfl_up_sync(0xffu, v, off);
                if (lane >= off) v += y;
            }
            warpsum[lane] = v;
        }
        __syncthreads();
        int texcl = x - s4 + (w ? warpsum[w - 1] : 0);
        int total = warpsum[7];

        if (tid == 0) {
            volatile int* st = g_sstate;
            if (b == 0) {
                st[0] = (total << 2) | 2;
                s_pre = 0;
            } else {
                st[b] = (total << 2) | 1;
                int pre = 0;
                int j = b - 1;
                while (j >= 0) {
                    int v = st[j];
                    int f = v & 3;
                    if (f == 2) { pre += (v >> 2); break; }
                    if (f == 1) { pre += (v >> 2); --j; }
                }
                st[b] = ((total + pre) << 2) | 2;
                s_pre = pre;
            }
        }
        __syncthreads();
        int e0 = texcl + s_pre;
        int sj[4] = {s1, s2, s3, s4};
        #pragma unroll
        for (int j = 0; j < 4; ++j) {
            int idx = base + j;
            if (idx < n) {
                g_roff[idx + 1] = e0 + sj[j];
                g_fill[idx] = e0 + (j ? sj[j - 1] : 0);
                g_outr[idx] = rsqrtf(fmaxf((float)o[j], 1.0f));
                g_sin[idx]  = rsqrtf(fmaxf((float)c[j], 1.0f));
                g_cnt[idx]  = 0;
                g_outd[idx] = 0;
            }
        }
        if (b == 0 && tid == 0) g_roff[0] = 0;
        __threadfence();
        __syncthreads();
        if (tid == 0) atomicAdd(&g_done_ctr, 1);
        return;
    }

    // =================== persistent GEMM worker ===================
    extern __shared__ __align__(128) char smraw[];
    __half* base = (__half*)smraw;
    uint32_t sb = sptr(smraw);
    __shared__ int s_next;

    int wid = tid >> 5, lane = tid & 31;
    int wm = wid & 3, wn = wid >> 2;

    if (tid == 0) s_next = atomicAdd(&g_tilectr, 1);
    __syncthreads();
    int cur = s_next;

    float acc[2][8][4];
    #pragma unroll
    for (int i = 0; i < 2; ++i)
        #pragma unroll
        for (int j = 0; j < 8; ++j)
            #pragma unroll
            for (int q = 0; q < 4; ++q) acc[i][j][q] = 0.f;

    if (cur < NT) {
        {
            int mB = (cur >> 2) * 128, nB = (cur & 3) * 128;
            load_stage(sb, 0, 0, mB, nB, n, tid); cp_commit();
            load_stage(sb, 1, 1, mB, nB, n, tid); cp_commit();
            load_stage(sb, 2, 2, mB, nB, n, tid); cp_commit();
        }
        while (cur < NT) {
            int mBase = (cur >> 2) * 128;
            int tn = cur & 3;
            int nBase = tn * 128;
            int nxt = NT;

            #pragma unroll 1
            for (int it = 0; it < 8; ++it) {
                if (it < 6 || nxt < NT) cp_wait2();
                else if (it == 6) cp_wait1();
                else cp_wait0();
                __syncthreads();
                if (it == 4 && tid == 0) s_next = atomicAdd(&g_tilectr, 1);
                if (it == 5) nxt = s_next;

                if (it <= 4) {
                    load_stage(sb, (it + 3) & 3, it + 3, mBase, nBase, n, tid);
                    cp_commit();
                } else if (nxt < NT) {
                    int m2 = (nxt >> 2) * 128, n2 = (nxt & 3) * 128;
                    load_stage(sb, (it + 3) & 3, it - 5, m2, n2, n, tid);
                    cp_commit();
                }

                int st = it & 3;
                #pragma unroll
                for (int kt = 0; kt < 2; ++kt) {
                    int ks = kt * 16;
                    unsigned aH[2][4];
                    #pragma unroll
                    for (int mt = 0; mt < 2; ++mt) {
                        int r = wm * 32 + mt * 16 + (lane & 15);
                        int c = ks + (lane >> 4) * 8;
                        ldsm4(aH[mt], sptr(base + AH_OFF(st) + r * A_STRIDE + c));
                    }
                    #pragma unroll
                    for (int nc = 0; nc < 4; ++nc) {
                        int rB = ks + (lane & 15);
                        int cB = wn * 64 + nc * 16 + (lane >> 4) * 8;
                        unsigned bH[4];
                        ldsm4t(bH, sptr(base + BH_OFF(st) + rB * B_STRIDE + cB));
                        #pragma unroll
                        for (int mt = 0; mt < 2; ++mt) {
                            mma_f16(acc[mt][nc * 2],     aH[mt], bH[0], bH[1]);
                            mma_f16(acc[mt][nc * 2 + 1], aH[mt], bH[2], bH[3]);
                        }
                    }
                }
            }

            // epilogue for tile cur: fp16 to g_h0 (tn<2) or g_h1 (tn>=2)
            __half* dstp = (tn < 2) ? g_h0 : g_h1;
            #pragma unroll
            for (int mt = 0; mt < 2; ++mt) {
                int r0 = mBase + wm * 32 + mt * 16 + (lane >> 2);
                int r1 = r0 + 8;
                #pragma unroll
                for (int nt = 0; nt < 8; ++nt) {
                    int cl = wn * 64 + nt * 8 + (lane & 3) * 2;
                    int c = (tn & 1) * 128 + cl;
                    float* d = acc[mt][nt];
                    if (r0 < n) {
                        __half2 v = __floats2half2_rn(d[0], d[1]);
                        *(unsigned*)(dstp + (size_t)r0 * F + c) = *(unsigned*)&v;
                    }
                    if (r1 < n) {
                        __half2 v = __floats2half2_rn(d[2], d[3]);
                        *(unsigned*)(dstp + (size_t)r1 * F + c) = *(unsigned*)&v;
                    }
                    d[0] = d[1] = d[2] = d[3] = 0.f;
                }
            }
            cur = nxt;
        }
    }

    // =================== dynamic CSR fill (gated on scan) ===================
    if (tid == 0) {
        while (*((volatile int*)&g_done_ctr) < NB) __nanosleep(64);
    }
    __syncthreads();
    __threadfence();
    __shared__ int s_ec;
    while (true) {
        if (tid == 0) s_ec = atomicAdd(&g_edgectr, 1);
        __syncthreads();
        int c0 = s_ec * EPC;
        if (c0 >= e) break;
        int cend = min(c0 + EPC, e);
        for (int i = c0 + tid; i < cend; i += 256) {
            float w = e_w[i];
            int s = src[i];
            int p = atomicAdd(&g_fill[dst[i]], 1);
            g_esrc[p] = s;
            g_esc[p] = w * g_outr[s];
            out_tail[i] = w;             // e_w passthrough output
        }
        __syncthreads();
    }
}

// ---------------- final: persistent, dynamic row queue ---------------------
__global__ void __launch_bounds__(256)
final_kernel(const float* __restrict__ bias, float* __restrict__ out, int n) {
    if (blockIdx.x == 0) {
        if (threadIdx.x == 0) {          // restore counters for next replay
            g_done_ctr = 0;
            g_tilectr = 0;
            g_edgectr = 0;
        }
        if (threadIdx.x < 64) g_sstate[threadIdx.x] = 0;
    }
    int lane = threadIdx.x & 31;

    while (true) {
        int r0 = 0;
        if (lane == 0) r0 = atomicAdd(&g_rowctr, 2);
        r0 = __shfl_sync(0xffffffffu, r0, 0);
        if (r0 >= n) break;
        int rend = min(r0 + 2, n);

        for (int row = r0; row < rend; ++row) {
            int beg = g_roff[row], end = g_roff[row + 1];
            float a[8];
            #pragma unroll
            for (int j = 0; j < 8; ++j) a[j] = 0.f;

            for (int base = beg; base < end; base += 32) {
                int m = min(32, end - base);
                int sE = 0; float cE = 0.f;
                if (lane < m) { sE = g_esrc[base + lane]; cE = g_esc[base + lane]; }
                int j = 0;
                for (; j + 8 <= m; j += 8) {
                    uint4 d[8];
                    #pragma unroll
                    for (int u = 0; u < 8; ++u) {
                        int ss = __shfl_sync(0xffffffffu, sE, j + u);
                        d[u] = *(const uint4*)(g_h1 + (size_t)ss * F + lane * 8);
                    }
                    #pragma unroll
                    for (int u = 0; u < 8; ++u) {
                        float sc = __shfl_sync(0xffffffffu, cE, j + u);
                        float2 f0 = __half22float2(*(__half2*)&d[u].x);
                        float2 f1 = __half22float2(*(__half2*)&d[u].y);
                        float2 f2 = __half22float2(*(__half2*)&d[u].z);
                        float2 f3 = __half22float2(*(__half2*)&d[u].w);
                        a[0] += f0.x * sc; a[1] += f0.y * sc;
                        a[2] += f1.x * sc; a[3] += f1.y * sc;
                        a[4] += f2.x * sc; a[5] += f2.y * sc;
                        a[6] += f3.x * sc; a[7] += f3.y * sc;
                    }
                }
                for (; j < m; ++j) {
                    int   ss = __shfl_sync(0xffffffffu, sE, j);
                    float sc = __shfl_sync(0xffffffffu, cE, j);
                    uint4 d = *(const uint4*)(g_h1 + (size_t)ss * F + lane * 8);
                    float2 f0 = __half22float2(*(__half2*)&d.x);
                    float2 f1 = __half22float2(*(__half2*)&d.y);
                    float2 f2 = __half22float2(*(__half2*)&d.z);
                    float2 f3 = __half22float2(*(__half2*)&d.w);
                    a[0] += f0.x * sc; a[1] += f0.y * sc;
                    a[2] += f1.x * sc; a[3] += f1.y * sc;
                    a[4] += f2.x * sc; a[5] += f2.y * sc;
                    a[6] += f3.x * sc; a[7] += f3.y * sc;
                }
            }

            float si = g_sin[row];
            uint4 h = *(const uint4*)(g_h0 + (size_t)row * F + lane * 8);
            float2 s0 = __half22float2(*(__half2*)&h.x);
            float2 s1 = __half22float2(*(__half2*)&h.y);
            float2 s2 = __half22float2(*(__half2*)&h.z);
            float2 s3 = __half22float2(*(__half2*)&h.w);
            float4 b0 = *(const float4*)(bias + lane * 8);
            float4 b1 = *(const float4*)(bias + lane * 8 + 4);
            float4 o0, o1;
            o0.x = s0.x + si * (a[0] + b0.x); o0.y = s0.y + si * (a[1] + b0.y);
            o0.z = s1.x + si * (a[2] + b0.z); o0.w = s1.y + si * (a[3] + b0.w);
            o1.x = s2.x + si * (a[4] + b1.x); o1.y = s2.y + si * (a[5] + b1.y);
            o1.z = s3.x + si * (a[6] + b1.z); o1.w = s3.y + si * (a[7] + b1.w);
            float* op = out + (size_t)row * F + lane * 8;
            *(float4*)(op)     = o0;
            *(float4*)(op + 4) = o1;
        }
    }
}

// ---------------- launch ----------------
extern "C" void kernel_launch(void* const* d_in, const int* in_sizes, int n_in,
                              void* d_out, int out_size) {
    const float* feature = (const float*)d_in[0];
    const float* e_w     = (const float*)d_in[1];
    const float* W_self  = (const float*)d_in[4];
    const float* W       = (const float*)d_in[5];
    const float* b       = (const float*)d_in[6];
    const int*   src     = (const int*)d_in[7];
    const int*   dst     = (const int*)d_in[8];
    float*       out     = (float*)d_out;

    int n = in_sizes[0] / F;
    int e = in_sizes[1];
    int q = n * (F / 4);

    static bool init = false;
    if (!init) {
        cudaFuncSetAttribute(gemmfill_kernel,
                             cudaFuncAttributeMaxDynamicSharedMemorySize, SMEM_DYN);
        init = true;
    }

    // K1: fused hist | convert feature | convert W (4 items/thread)
    int HB = (e + 1023) / 1024;
    int CB = (q + 1023) / 1024;
    int WB = (F * F + 255) / 256;
    phaseA_kernel<<<HB + CB + WB, 256>>>(src, dst, feature, W_self, W,
                                         e, q, HB, CB);

    // K2: scan blocks + persistent GEMM workers + dynamic fill, one launch
    int NB = (n + 1023) / 1024;          // <= 64 (scan role blocks)
    int NT = ((n + 127) / 128) * 4;      // gemm tiles
    int WORKERS = 304;                   // 2 CTAs/SM
    gemmfill_kernel<<<NB + WORKERS, 256, SMEM_DYN>>>(src, dst, e_w,
                                                     out + (size_t)n * F,
                                                     n, e, NT, NB);

    // K3: final gather + epilogue (persistent, dynamic row queue)
    final_kernel<<<740, 256>>>(b, out, n);
}

// round 15
// speedup vs baseline: 1.2731x; 1.0302x over previous
#include <cuda_runtime.h>
#include <cuda_bf16.h>
#include <cuda_fp16.h>
#include <math.h>
#include <stdint.h>

#define F 256
#define NW 512           // fused B width: [W_self | W]
#define N_MAX 50048
#define E_MAX 800256
#define EPC 2048         // edges per fill chunk
#define HEPC 4096        // edges per hist chunk

// -------- device scratch (zero-initialized at module load; replay invariants
// restored by the roles noted below) --------
__device__ float g_sin[N_MAX];               // in_deg^-1/2
__device__ float g_outr[N_MAX];              // out_deg^-1/2
__device__ int   g_cnt[N_MAX];
__device__ int   g_outd[N_MAX];
__device__ int   g_fill[N_MAX];
__device__ int   g_roff[N_MAX + 1];
__device__ int   g_esrc[E_MAX];
__device__ float g_esc[E_MAX];
__device__ int   g_sstate[64];               // lookback scan state
__device__ int   g_done_ctr;                 // scan-complete counter
__device__ int   g_histctr;                  // dynamic hist-chunk queue
__device__ int   g_histdone;                 // hist-complete counter
__device__ int   g_rowctr;                   // dynamic row queue (final)
__device__ int   g_tilectr;                  // dynamic tile queue (gemm)
__device__ int   g_edgectr;                  // dynamic edge-chunk queue (fill)

__device__ __half g_featH[(size_t)N_MAX * F];       // fp16(feature)
__device__ __half g_wb[F * NW];                     // [k][n512] = [W_self | W]
__device__ __half g_h0[(size_t)N_MAX * F];          // feature@W_self (fp16)
__device__ __half g_h1[(size_t)N_MAX * F];          // feature@W      (fp16)

// -------- helpers --------
__device__ __forceinline__ uint32_t sptr(const void* p) {
    return (uint32_t)__cvta_generic_to_shared(p);
}
__device__ __forceinline__ void ldsm4(unsigned r[4], uint32_t a) {
    asm volatile("ldmatrix.sync.aligned.m8n8.x4.shared.b16 {%0,%1,%2,%3}, [%4];\n"
        : "=r"(r[0]), "=r"(r[1]), "=r"(r[2]), "=r"(r[3]) : "r"(a));
}
__device__ __forceinline__ void ldsm4t(unsigned r[4], uint32_t a) {
    asm volatile("ldmatrix.sync.aligned.m8n8.x4.trans.shared.b16 {%0,%1,%2,%3}, [%4];\n"
        : "=r"(r[0]), "=r"(r[1]), "=r"(r[2]), "=r"(r[3]) : "r"(a));
}
__device__ __forceinline__ void mma_f16(float* d, const unsigned a[4],
                                        unsigned b0, unsigned b1) {
    asm volatile(
        "mma.sync.aligned.m16n8k16.row.col.f32.f16.f16.f32 "
        "{%0,%1,%2,%3}, {%4,%5,%6,%7}, {%8,%9}, {%0,%1,%2,%3};\n"
        : "+f"(d[0]), "+f"(d[1]), "+f"(d[2]), "+f"(d[3])
        : "r"(a[0]), "r"(a[1]), "r"(a[2]), "r"(a[3]), "r"(b0), "r"(b1));
}
__device__ __forceinline__ void cp16(uint32_t dst, const void* src) {
    asm volatile("cp.async.cg.shared.global [%0], [%1], 16;\n" :: "r"(dst), "l"(src));
}
__device__ __forceinline__ void cp16z(uint32_t dst, const void* src, int sz) {
    asm volatile("cp.async.cg.shared.global [%0], [%1], 16, %2;\n"
                 :: "r"(dst), "l"(src), "r"(sz));
}
__device__ __forceinline__ void cp_commit() {
    asm volatile("cp.async.commit_group;\n" ::: "memory");
}
__device__ __forceinline__ void cp_wait2() {
    asm volatile("cp.async.wait_group 2;\n" ::: "memory");
}
__device__ __forceinline__ void cp_wait1() {
    asm volatile("cp.async.wait_group 1;\n" ::: "memory");
}
__device__ __forceinline__ void cp_wait0() {
    asm volatile("cp.async.wait_group 0;\n" ::: "memory");
}

// ---------------- phaseA: pure streaming converts (no atomics) -------------
__global__ void phaseA_kernel(const float* __restrict__ feat,
                              const float* __restrict__ Ws,
                              const float* __restrict__ Wn,
                              int q, int CB) {
    int b = blockIdx.x, t = threadIdx.x;
    if (b < CB) {
        int base = b * 1024 + t;
        float4 v[4];
        #pragma unroll
        for (int u = 0; u < 4; ++u) {
            int i = base + u * 256;
            if (i < q) v[u] = ((const float4*)feat)[i];
        }
        #pragma unroll
        for (int u = 0; u < 4; ++u) {
            int i = base + u * 256;
            if (i < q) {
                __half2 H0 = __floats2half2_rn(v[u].x, v[u].y);
                __half2 H1 = __floats2half2_rn(v[u].z, v[u].w);
                ((uint2*)g_featH)[i] = make_uint2(*(unsigned*)&H0, *(unsigned*)&H1);
            }
        }
    } else {
        int i = (b - CB) * 256 + t;
        if (i < F * F) {
            int k = i >> 8, nn = i & 255;
            g_wb[k * NW + nn]       = __float2half_rn(Ws[i]);
            g_wb[k * NW + 256 + nn] = __float2half_rn(Wn[i]);
        }
    }
}

// ------- mega kernel: hist+scan roles co-running with persistent GEMM ------
#define A_STRIDE 40
#define B_STRIDE 136
#define ST_ELEMS 9472            // 128*40 + 32*136
#define AH_OFF(s) ((s) * ST_ELEMS)
#define BH_OFF(s) ((s) * ST_ELEMS + 5120)
#define NSTAGE 4
#define SMEM_DYN (NSTAGE * ST_ELEMS * 2)

__device__ __forceinline__ void load_stage(uint32_t sb, int stage, int kc,
                                           int mBase, int nBase, int n, int tid) {
    int k0 = kc * 32;
    #pragma unroll
    for (int u = 0; u < 2; ++u) {
        int idx = u * 256 + tid;
        int row = idx >> 2, un = idx & 3;
        int gr = mBase + row;
        int grc = min(gr, n - 1);
        size_t go = (size_t)grc * F + k0 + un * 8;
        int sz = (gr < n) ? 16 : 0;
        uint32_t doff = (uint32_t)(row * A_STRIDE + un * 8) * 2;
        cp16z(sb + (uint32_t)AH_OFF(stage) * 2 + doff, g_featH + go, sz);
    }
    #pragma unroll
    for (int u = 0; u < 2; ++u) {
        int idx = u * 256 + tid;
        int row = idx >> 4, un = idx & 15;
        size_t go = (size_t)(k0 + row) * NW + nBase + un * 8;
        uint32_t doff = (uint32_t)(row * B_STRIDE + un * 8) * 2;
        cp16(sb + (uint32_t)BH_OFF(stage) * 2 + doff, g_wb + go);
    }
}

__global__ void __launch_bounds__(256, 2)
gemmfill_kernel(const int* __restrict__ src,
                const int* __restrict__ dst,
                const float* __restrict__ e_w,
                float* __restrict__ out_tail,
                int n, int e, int NT, int NB) {
    int b = blockIdx.x, tid = threadIdx.x;

    // ============ hist + scan role (blocks [0, NB), all wave-1) ============
    if (b < NB) {
        __shared__ int warpsum[8];
        __shared__ int s_pre;
        __shared__ int s_hc;
        int lane = tid & 31, w = tid >> 5;
        if (b == 0 && tid == 0) g_rowctr = 0;   // reset row queue for final

        // --- dynamic histogram chunks (co-runs with GEMM workers) ---
        while (true) {
            if (tid == 0) s_hc = atomicAdd(&g_histctr, 1);
            __syncthreads();
            int c0 = s_hc * HEPC;
            if (c0 >= e) break;
            int cend = min(c0 + HEPC, e);
            for (int i = c0 + tid; i < cend; i += 256) {
                atomicAdd(&g_cnt[dst[i]], 1);
                atomicAdd(&g_outd[src[i]], 1);
            }
            __syncthreads();
        }
        __threadfence();
        __syncthreads();
        if (tid == 0) atomicAdd(&g_histdone, 1);
        if (tid == 0) {
            while (*((volatile int*)&g_histdone) < NB) __nanosleep(64);
        }
        __syncthreads();
        __threadfence();

        // --- scan (warp-shuffle + decoupled lookback) ---
        int base = b * 1024 + tid * 4;
        int c[4], o[4];
        #pragma unroll
        for (int j = 0; j < 4; ++j) {
            int idx = base + j;
            c[j] = (idx < n) ? g_cnt[idx] : 0;
            o[j] = (idx < n) ? g_outd[idx] : 0;
        }
        int s1 = c[0], s2 = s1 + c[1], s3 = s2 + c[2], s4 = s3 + c[3];
        int x = s4;
        #pragma unroll
        for (int off = 1; off < 32; off <<= 1) {
            int y = __shfl_up_sync(0xffffffffu, x, off);
            if (lane >= off) x += y;
        }
        if (lane == 31) warpsum[w] = x;
        __syncthreads();
        if (w == 0 && lane < 8) {
            int v = warpsum[lane];
            #pragma unroll
            for (int off = 1; off < 8; off <<= 1) {
                int y = __shfl_up_sync(0xffu, v, off);
                if (lane >= off) v += y;
            }
            warpsum[lane] = v;
        }
        __syncthreads();
        int texcl = x - s4 + (w ? warpsum[w - 1] : 0);
        int total = warpsum[7];

        if (tid == 0) {
            volatile int* st = g_sstate;
            if (b == 0) {
                st[0] = (total << 2) | 2;
                s_pre = 0;
            } else {
                st[b] = (total << 2) | 1;
                int pre = 0;
                int j = b - 1;
                while (j >= 0) {
                    int v = st[j];
                    int f = v & 3;
                    if (f == 2) { pre += (v >> 2); break; }
                    if (f == 1) { pre += (v >> 2); --j; }
                }
                st[b] = ((total + pre) << 2) | 2;
                s_pre = pre;
            }
        }
        __syncthreads();
        int e0 = texcl + s_pre;
        int sj[4] = {s1, s2, s3, s4};
        #pragma unroll
        for (int j = 0; j < 4; ++j) {
            int idx = base + j;
            if (idx < n) {
                g_roff[idx + 1] = e0 + sj[j];
                g_fill[idx] = e0 + (j ? sj[j - 1] : 0);
                g_outr[idx] = rsqrtf(fmaxf((float)o[j], 1.0f));
                g_sin[idx]  = rsqrtf(fmaxf((float)c[j], 1.0f));
                g_cnt[idx]  = 0;                  // restore zero invariant
                g_outd[idx] = 0;
            }
        }
        if (b == 0 && tid == 0) g_roff[0] = 0;
        __threadfence();
        __syncthreads();
        if (tid == 0) atomicAdd(&g_done_ctr, 1);
        return;
    }

    // =================== persistent GEMM worker ===================
    extern __shared__ __align__(128) char smraw[];
    __half* base = (__half*)smraw;
    uint32_t sb = sptr(smraw);
    __shared__ int s_next;

    int wid = tid >> 5, lane = tid & 31;
    int wm = wid & 3, wn = wid >> 2;

    if (tid == 0) s_next = atomicAdd(&g_tilectr, 1);
    __syncthreads();
    int cur = s_next;

    float acc[2][8][4];
    #pragma unroll
    for (int i = 0; i < 2; ++i)
        #pragma unroll
        for (int j = 0; j < 8; ++j)
            #pragma unroll
            for (int q = 0; q < 4; ++q) acc[i][j][q] = 0.f;

    if (cur < NT) {
        {
            int mB = (cur >> 2) * 128, nB = (cur & 3) * 128;
            load_stage(sb, 0, 0, mB, nB, n, tid); cp_commit();
            load_stage(sb, 1, 1, mB, nB, n, tid); cp_commit();
            load_stage(sb, 2, 2, mB, nB, n, tid); cp_commit();
        }
        while (cur < NT) {
            int mBase = (cur >> 2) * 128;
            int tn = cur & 3;
            int nBase = tn * 128;
            int nxt = NT;

            #pragma unroll 1
            for (int it = 0; it < 8; ++it) {
                if (it < 6 || nxt < NT) cp_wait2();
                else if (it == 6) cp_wait1();
                else cp_wait0();
                __syncthreads();
                if (it == 4 && tid == 0) s_next = atomicAdd(&g_tilectr, 1);
                if (it == 5) nxt = s_next;

                if (it <= 4) {
                    load_stage(sb, (it + 3) & 3, it + 3, mBase, nBase, n, tid);
                    cp_commit();
                } else if (nxt < NT) {
                    int m2 = (nxt >> 2) * 128, n2 = (nxt & 3) * 128;
                    load_stage(sb, (it + 3) & 3, it - 5, m2, n2, n, tid);
                    cp_commit();
                }

                int st = it & 3;
                #pragma unroll
                for (int kt = 0; kt < 2; ++kt) {
                    int ks = kt * 16;
                    unsigned aH[2][4];
                    #pragma unroll
                    for (int mt = 0; mt < 2; ++mt) {
                        int r = wm * 32 + mt * 16 + (lane & 15);
                        int c = ks + (lane >> 4) * 8;
                        ldsm4(aH[mt], sptr(base + AH_OFF(st) + r * A_STRIDE + c));
                    }
                    #pragma unroll
                    for (int nc = 0; nc < 4; ++nc) {
                        int rB = ks + (lane & 15);
                        int cB = wn * 64 + nc * 16 + (lane >> 4) * 8;
                        unsigned bH[4];
                        ldsm4t(bH, sptr(base + BH_OFF(st) + rB * B_STRIDE + cB));
                        #pragma unroll
                        for (int mt = 0; mt < 2; ++mt) {
                            mma_f16(acc[mt][nc * 2],     aH[mt], bH[0], bH[1]);
                            mma_f16(acc[mt][nc * 2 + 1], aH[mt], bH[2], bH[3]);
                        }
                    }
                }
            }

            // epilogue for tile cur
            __half* dstp = (tn < 2) ? g_h0 : g_h1;
            #pragma unroll
            for (int mt = 0; mt < 2; ++mt) {
                int r0 = mBase + wm * 32 + mt * 16 + (lane >> 2);
                int r1 = r0 + 8;
                #pragma unroll
                for (int nt = 0; nt < 8; ++nt) {
                    int cl = wn * 64 + nt * 8 + (lane & 3) * 2;
                    int c = (tn & 1) * 128 + cl;
                    float* d = acc[mt][nt];
                    if (r0 < n) {
                        __half2 v = __floats2half2_rn(d[0], d[1]);
                        *(unsigned*)(dstp + (size_t)r0 * F + c) = *(unsigned*)&v;
                    }
                    if (r1 < n) {
                        __half2 v = __floats2half2_rn(d[2], d[3]);
                        *(unsigned*)(dstp + (size_t)r1 * F + c) = *(unsigned*)&v;
                    }
                    d[0] = d[1] = d[2] = d[3] = 0.f;
                }
            }
            cur = nxt;
        }
    }

    // =================== dynamic CSR fill (gated on scan) ===================
    if (tid == 0) {
        while (*((volatile int*)&g_done_ctr) < NB) __nanosleep(64);
    }
    __syncthreads();
    __threadfence();
    __shared__ int s_ec;
    while (true) {
        if (tid == 0) s_ec = atomicAdd(&g_edgectr, 1);
        __syncthreads();
        int c0 = s_ec * EPC;
        if (c0 >= e) break;
        int cend = min(c0 + EPC, e);
        for (int i = c0 + tid; i < cend; i += 256) {
            float w = e_w[i];
            int s = src[i];
            int p = atomicAdd(&g_fill[dst[i]], 1);
            g_esrc[p] = s;
            g_esc[p] = w * g_outr[s];
            out_tail[i] = w;             // e_w passthrough output
        }
        __syncthreads();
    }
}

// ---------------- final: persistent, dynamic row queue ---------------------
__global__ void __launch_bounds__(256)
final_kernel(const float* __restrict__ bias, float* __restrict__ out, int n) {
    if (blockIdx.x == 0) {
        if (threadIdx.x == 0) {          // restore counters for next replay
            g_done_ctr = 0;
            g_tilectr = 0;
            g_edgectr = 0;
            g_histctr = 0;
            g_histdone = 0;
        }
        if (threadIdx.x < 64) g_sstate[threadIdx.x] = 0;
    }
    int lane = threadIdx.x & 31;

    while (true) {
        int r0 = 0;
        if (lane == 0) r0 = atomicAdd(&g_rowctr, 2);
        r0 = __shfl_sync(0xffffffffu, r0, 0);
        if (r0 >= n) break;
        int rend = min(r0 + 2, n);

        for (int row = r0; row < rend; ++row) {
            int beg = g_roff[row], end = g_roff[row + 1];
            float a[8];
            #pragma unroll
            for (int j = 0; j < 8; ++j) a[j] = 0.f;

            for (int base = beg; base < end; base += 32) {
                int m = min(32, end - base);
                int sE = 0; float cE = 0.f;
                if (lane < m) { sE = g_esrc[base + lane]; cE = g_esc[base + lane]; }
                int j = 0;
                for (; j + 8 <= m; j += 8) {
                    uint4 d[8];
                    #pragma unroll
                    for (int u = 0; u < 8; ++u) {
                        int ss = __shfl_sync(0xffffffffu, sE, j + u);
                        d[u] = *(const uint4*)(g_h1 + (size_t)ss * F + lane * 8);
                    }
                    #pragma unroll
                    for (int u = 0; u < 8; ++u) {
                        float sc = __shfl_sync(0xffffffffu, cE, j + u);
                        float2 f0 = __half22float2(*(__half2*)&d[u].x);
                        float2 f1 = __half22float2(*(__half2*)&d[u].y);
                        float2 f2 = __half22float2(*(__half2*)&d[u].z);
                        float2 f3 = __half22float2(*(__half2*)&d[u].w);
                        a[0] += f0.x * sc; a[1] += f0.y * sc;
                        a[2] += f1.x * sc; a[3] += f1.y * sc;
                        a[4] += f2.x * sc; a[5] += f2.y * sc;
                        a[6] += f3.x * sc; a[7] += f3.y * sc;
                    }
                }
                for (; j < m; ++j) {
                    int   ss = __shfl_sync(0xffffffffu, sE, j);
                    float sc = __shfl_sync(0xffffffffu, cE, j);
                    uint4 d = *(const uint4*)(g_h1 + (size_t)ss * F + lane * 8);
                    float2 f0 = __half22float2(*(__half2*)&d.x);
                    float2 f1 = __half22float2(*(__half2*)&d.y);
                    float2 f2 = __half22float2(*(__half2*)&d.z);
                    float2 f3 = __half22float2(*(__half2*)&d.w);
                    a[0] += f0.x * sc; a[1] += f0.y * sc;
                    a[2] += f1.x * sc; a[3] += f1.y * sc;
                    a[4] += f2.x * sc; a[5] += f2.y * sc;
                    a[6] += f3.x * sc; a[7] += f3.y * sc;
                }
            }

            float si = g_sin[row];
            uint4 h = *(const uint4*)(g_h0 + (size_t)row * F + lane * 8);
            float2 s0 = __half22float2(*(__half2*)&h.x);
            float2 s1 = __half22float2(*(__half2*)&h.y);
            float2 s2 = __half22float2(*(__half2*)&h.z);
            float2 s3 = __half22float2(*(__half2*)&h.w);
            float4 b0 = *(const float4*)(bias + lane * 8);
            float4 b1 = *(const float4*)(bias + lane * 8 + 4);
            float4 o0, o1;
            o0.x = s0.x + si * (a[0] + b0.x); o0.y = s0.y + si * (a[1] + b0.y);
            o0.z = s1.x + si * (a[2] + b0.z); o0.w = s1.y + si * (a[3] + b0.w);
            o1.x = s2.x + si * (a[4] + b1.x); o1.y = s2.y + si * (a[5] + b1.y);
            o1.z = s3.x + si * (a[6] + b1.z); o1.w = s3.y + si * (a[7] + b1.w);
            float* op = out + (size_t)row * F + lane * 8;
            *(float4*)(op)     = o0;
            *(float4*)(op + 4) = o1;
        }
    }
}

// ---------------- launch ----------------
extern "C" void kernel_launch(void* const* d_in, const int* in_sizes, int n_in,
                              void* d_out, int out_size) {
    const float* feature = (const float*)d_in[0];
    const float* e_w     = (const float*)d_in[1];
    const float* W_self  = (const float*)d_in[4];
    const float* W       = (const float*)d_in[5];
    const float* b       = (const float*)d_in[6];
    const int*   src     = (const int*)d_in[7];
    const int*   dst     = (const int*)d_in[8];
    float*       out     = (float*)d_out;

    int n = in_sizes[0] / F;
    int e = in_sizes[1];
    int q = n * (F / 4);

    static bool init = false;
    if (!init) {
        cudaFuncSetAttribute(gemmfill_kernel,
                             cudaFuncAttributeMaxDynamicSharedMemorySize, SMEM_DYN);
        init = true;
    }

    // K1: streaming converts only (no atomics)
    int CB = (q + 1023) / 1024;
    int WB = (F * F + 255) / 256;
    phaseA_kernel<<<CB + WB, 256>>>(feature, W_self, W, q, CB);

    // K2: hist+scan blocks co-running with persistent GEMM + dynamic fill
    int NB = (n + 1023) / 1024;          // <= 64 (hist/scan role blocks)
    int NT = ((n + 127) / 128) * 4;      // gemm tiles
    int WORKERS = 296;
    gemmfill_kernel<<<NB + WORKERS, 256, SMEM_DYN>>>(src, dst, e_w,
                                                     out + (size_t)n * F,
                                                     n, e, NT, NB);

    // K3: final gather + epilogue (persistent, dynamic row queue)
    final_kernel<<<740, 256>>>(b, out, n);
}